// round 9
// baseline (speedup 1.0000x reference)
#include <cuda_runtime.h>
#include <cuda_fp16.h>
#include <math.h>
#include <stdint.h>

#define BNB  2
#define NPTS 2048
#define CCH  256
#define NH   4
#define HDIM 64
#define NL   4
#define BHN  (BNB*NH)
#define EPSBN 1e-5f

// ---------------- scratch (device globals; no allocation allowed) -------------
__device__ float g_bufA[BNB*CCH*NPTS];
__device__ float g_bufB[BNB*CCH*NPTS];
__device__ float g_q  [BHN*HDIM*NPTS];
__device__ float g_k  [BHN*HDIM*NPTS];
__device__ float g_v  [BHN*HDIM*NPTS];
__device__ float g_S  [(size_t)BHN*NPTS*NPTS];   // raw scores (mostly L2-resident)
__device__ float g_mx [BHN*NPTS];
__device__ float g_rs [BHN*NPTS];

// fast exp on the FMA pipe
__device__ __forceinline__ float fexp(float x) {
    x = fmaxf(x, -80.f);
    float t = fmaf(x, 1.44269504f, 12582912.f);
    int   e = __float_as_int(t) << 23;
    float r = t - 12582912.f;
    float f = fmaf(x, 1.44269504f, -r);
    float p = 1.54035304e-4f;
    p = fmaf(p, f, 1.33335581e-3f);
    p = fmaf(p, f, 9.61812911e-3f);
    p = fmaf(p, f, 5.55041087e-2f);
    p = fmaf(p, f, 2.40226507e-1f);
    p = fmaf(p, f, 6.93147181e-1f);
    p = fmaf(p, f, 1.0f);
    return __int_as_float(__float_as_int(p) + e);
}

__device__ __forceinline__ uint32_t h2(float a, float b) {
    __half2 h = __floats2half2_rn(a, b);
    return *reinterpret_cast<uint32_t*>(&h);
}

#define MMA_F16(c, a, b)                                                         \
    asm volatile("mma.sync.aligned.m16n8k16.row.col.f32.f16.f16.f32 "            \
                 "{%0,%1,%2,%3},{%4,%5,%6,%7},{%8,%9},{%0,%1,%2,%3};"            \
                 : "+f"((c)[0]), "+f"((c)[1]), "+f"((c)[2]), "+f"((c)[3])        \
                 : "r"((a)[0]), "r"((a)[1]), "r"((a)[2]), "r"((a)[3]),           \
                   "r"((b)[0]), "r"((b)[1]))

// ---------------- transposes ----------------
__global__ void k_transpose_in(const float* __restrict__ x, float* __restrict__ h) {
    __shared__ float tile[32][33];
    int b = blockIdx.z;
    int n0 = blockIdx.x * 32, c0 = blockIdx.y * 32;
    int tx = threadIdx.x, ty = threadIdx.y;
    for (int i = ty; i < 32; i += 8)
        tile[i][tx] = x[(size_t)b*NPTS*CCH + (size_t)(n0+i)*CCH + c0 + tx];
    __syncthreads();
    for (int i = ty; i < 32; i += 8)
        h[(size_t)b*CCH*NPTS + (size_t)(c0+i)*NPTS + n0 + tx] = tile[tx][i];
}

__global__ void k_transpose_out(const float* __restrict__ h, float* __restrict__ out) {
    __shared__ float tile[32][33];
    int b = blockIdx.z;
    int c0 = blockIdx.x * 32, n0 = blockIdx.y * 32;
    int tx = threadIdx.x, ty = threadIdx.y;
    for (int i = ty; i < 32; i += 8)
        tile[i][tx] = h[(size_t)b*CCH*NPTS + (size_t)(c0+i)*NPTS + n0 + tx];
    __syncthreads();
    for (int i = ty; i < 32; i += 8)
        out[(size_t)b*NPTS*CCH + (size_t)(n0+i)*CCH + c0 + tx] = tile[tx][i];
}

// ---------------- MLP/proj GEMM: tile 64o x 64n, K step 16, padded smem -------
__global__ __launch_bounds__(256)
void k_mlp(const float* __restrict__ W, const float* __restrict__ in,
           float* __restrict__ out, const float* __restrict__ bvec,
           const float* __restrict__ gvec, const float* __restrict__ bevec,
           int relu) {
    __shared__ float As[64][20];    // stride 20 -> 2-way max on A reads
    __shared__ float Bs[16][68];
    int b  = blockIdx.z;
    int n0 = blockIdx.x * 64, o0 = blockIdx.y * 64;
    int t  = threadIdx.x, tx = t & 15, ty = t >> 4;
    const float* inb = in + (size_t)b*CCH*NPTS;
    int aoo = t >> 2, akk = (t & 3) * 4;
    int bkk = t >> 4, bnn = (t & 15) * 4;
    float acc[4][4] = {};
    for (int kc = 0; kc < CCH; kc += 16) {
        *(float4*)&As[aoo][akk] = *(const float4*)&W[(size_t)(o0+aoo)*CCH + kc + akk];
        *(float4*)&Bs[bkk][bnn] = *(const float4*)&inb[(size_t)(kc+bkk)*NPTS + n0 + bnn];
        __syncthreads();
        #pragma unroll
        for (int kk = 0; kk < 16; kk++) {
            float a[4];
            #pragma unroll
            for (int i = 0; i < 4; i++) a[i] = As[ty*4+i][kk];
            float4 bv = *(float4*)&Bs[kk][tx*4];
            float bb[4] = {bv.x, bv.y, bv.z, bv.w};
            #pragma unroll
            for (int i = 0; i < 4; i++)
                #pragma unroll
                for (int j = 0; j < 4; j++)
                    acc[i][j] = fmaf(a[i], bb[j], acc[i][j]);
        }
        __syncthreads();
    }
    float* outb = out + (size_t)b*CCH*NPTS;
    #pragma unroll
    for (int i = 0; i < 4; i++) {
        int o = o0 + ty*4 + i;
        float alpha = 1.f, beta = 0.f;
        if (gvec) { alpha = gvec[o] * rsqrtf(1.f + EPSBN); beta = bvec[o]*alpha + bevec[o]; }
        else if (bvec) beta = bvec[o];
        float4 s;
        s.x = fmaf(acc[i][0], alpha, beta);
        s.y = fmaf(acc[i][1], alpha, beta);
        s.z = fmaf(acc[i][2], alpha, beta);
        s.w = fmaf(acc[i][3], alpha, beta);
        if (relu) {
            s.x = fmaxf(s.x, 0.f); s.y = fmaxf(s.y, 0.f);
            s.z = fmaxf(s.z, 0.f); s.w = fmaxf(s.w, 0.f);
        }
        *(float4*)&outb[(size_t)o*NPTS + n0 + tx*4] = s;
    }
}

// ------- fused q/k/v head GEMMs: 64o x 64n, one B load, three weight passes ----
__global__ __launch_bounds__(256)
void k_qkv(const float* __restrict__ qw, const float* __restrict__ kw,
           const float* __restrict__ vw, const float* __restrict__ vbias,
           const float* __restrict__ in, float* __restrict__ qo,
           float* __restrict__ ko, float* __restrict__ vo, int l) {
    __shared__ float As[64][68];   // padded: A reads 2-way max
    __shared__ float Bs[64][68];
    int n0 = blockIdx.x * 64, bh = blockIdx.y, hh = bh & (NH-1);
    int t = threadIdx.x, tx = t & 15, ty = t >> 4;
    const float* inb = in + (size_t)bh * HDIM * NPTS;
    int vbase = (l*NH + hh) * HDIM;
    #pragma unroll
    for (int r = 0; r < 4; r++) {
        int u = r*1024 + t*4;
        int cc = u >> 6, nn = u & 63;
        *(float4*)&Bs[cc][nn] = *(const float4*)&inb[(size_t)cc*NPTS + n0 + nn];
    }
    for (int w = 0; w < 3; w++) {
        const float* W = (w == 0 ? qw : w == 1 ? kw : vw) + (size_t)(l*NH + hh)*HDIM*HDIM;
        __syncthreads();
        #pragma unroll
        for (int r = 0; r < 4; r++) {
            int u = r*1024 + t*4;
            int o = u >> 6, c4 = u & 63;
            *(float4*)&As[o][c4] = *(const float4*)&W[o*HDIM + c4];
        }
        __syncthreads();
        float acc[4][4] = {};
        #pragma unroll
        for (int cc = 0; cc < 64; cc++) {
            float a[4];
            #pragma unroll
            for (int i = 0; i < 4; i++) a[i] = As[ty*4+i][cc];
            float4 bv = *(float4*)&Bs[cc][tx*4];
            float bb[4] = {bv.x, bv.y, bv.z, bv.w};
            #pragma unroll
            for (int i = 0; i < 4; i++)
                #pragma unroll
                for (int j = 0; j < 4; j++)
                    acc[i][j] = fmaf(a[i], bb[j], acc[i][j]);
        }
        float* outb = (w == 0 ? qo : w == 1 ? ko : vo) + (size_t)bh * HDIM * NPTS;
        #pragma unroll
        for (int i = 0; i < 4; i++) {
            int o = ty*4 + i;
            float bb = (w == 2) ? vbias[vbase + o] : 0.f;
            float4 s = {acc[i][0]+bb, acc[i][1]+bb, acc[i][2]+bb, acc[i][3]+bb};
            *(float4*)&outb[(size_t)o*NPTS + n0 + tx*4] = s;
        }
    }
}

// ---- scores + online row stats, fp16 MMA: block = 64 n-rows x full m sweep ----
// q,k packed half2 along o (K dim). Writes raw fp32 S once; computes stats.
__global__ __launch_bounds__(256)
void k_scores_st(const float* __restrict__ q, const float* __restrict__ k,
                 float* __restrict__ S, float* __restrict__ mxv,
                 float* __restrict__ rsv) {
    __shared__ uint32_t Qh[32][72];    // [o2][n]  72%32==8 -> conflict-free frags
    __shared__ uint32_t Kh[32][136];   // [o2][m]  136%32==8
    __shared__ float Mred[64][8], Sred[64][8];
    int n0 = blockIdx.x * 64, bh = blockIdx.y;
    const float* qb = q + (size_t)bh * HDIM * NPTS;
    const float* kb = k + (size_t)bh * HDIM * NPTS;
    int t = threadIdx.x, warp = t >> 5, lane = t & 31;
    int gq = lane >> 2, tg = lane & 3;
    // persistent Q tile: 64o x 64n, packed pairs (2r, 2r+1) along o
    #pragma unroll
    for (int r = 0; r < 2; r++) {
        int u = r*256 + t;
        int rr = u >> 4, n4 = (u & 15) * 4;
        float4 q0 = *(const float4*)&qb[(size_t)(2*rr)*NPTS + n0 + n4];
        float4 q1 = *(const float4*)&qb[(size_t)(2*rr+1)*NPTS + n0 + n4];
        uint4 w = {h2(q0.x,q1.x), h2(q0.y,q1.y), h2(q0.z,q1.z), h2(q0.w,q1.w)};
        *(uint4*)&Qh[rr][n4] = w;
    }
    float stM[4][2], stS[4][2];
    #pragma unroll
    for (int i = 0; i < 4; i++)
        #pragma unroll
        for (int hf = 0; hf < 2; hf++) { stM[i][hf] = -1e30f; stS[i][hf] = 0.f; }
    float* Sb = S + (size_t)bh * NPTS * NPTS;

    for (int m0 = 0; m0 < NPTS; m0 += 128) {
        __syncthreads();
        #pragma unroll
        for (int r = 0; r < 4; r++) {
            int u = r*256 + t;
            int rr = u >> 5, m4 = (u & 31) * 4;
            float4 k0 = *(const float4*)&kb[(size_t)(2*rr)*NPTS + m0 + m4];
            float4 k1 = *(const float4*)&kb[(size_t)(2*rr+1)*NPTS + m0 + m4];
            uint4 w = {h2(k0.x,k1.x), h2(k0.y,k1.y), h2(k0.z,k1.z), h2(k0.w,k1.w)};
            *(uint4*)&Kh[rr][m4] = w;
        }
        __syncthreads();
        float acc[4][2][4];
        #pragma unroll
        for (int i = 0; i < 4; i++)
            #pragma unroll
            for (int j = 0; j < 2; j++)
                #pragma unroll
                for (int c = 0; c < 4; c++) acc[i][j][c] = 0.f;
        #pragma unroll
        for (int kh = 0; kh < 32; kh += 8) {    // 4 x k16 steps over K=64
            uint32_t a[4][4], b[2][2];
            #pragma unroll
            for (int ti = 0; ti < 4; ti++) {
                int nb = ti*16 + gq;
                a[ti][0] = Qh[kh+tg][nb];
                a[ti][1] = Qh[kh+tg][nb+8];
                a[ti][2] = Qh[kh+4+tg][nb];
                a[ti][3] = Qh[kh+4+tg][nb+8];
            }
            #pragma unroll
            for (int tj = 0; tj < 2; tj++) {
                int mb = warp*16 + tj*8 + gq;
                b[tj][0] = Kh[kh+tg][mb];
                b[tj][1] = Kh[kh+4+tg][mb];
            }
            #pragma unroll
            for (int ti = 0; ti < 4; ti++)
                #pragma unroll
                for (int tj = 0; tj < 2; tj++)
                    MMA_F16(acc[ti][tj], a[ti], b[tj]);
        }
        // store raw S + online stats
        #pragma unroll
        for (int ti = 0; ti < 4; ti++) {
            #pragma unroll
            for (int tj = 0; tj < 2; tj++) {
                int n = n0 + ti*16 + gq;
                int m = m0 + warp*16 + tj*8 + 2*tg;
                float2 lo = {acc[ti][tj][0], acc[ti][tj][1]};
                float2 hi = {acc[ti][tj][2], acc[ti][tj][3]};
                *(float2*)&Sb[(size_t)n*NPTS + m]     = lo;
                *(float2*)&Sb[(size_t)(n+8)*NPTS + m] = hi;
            }
            #pragma unroll
            for (int hf = 0; hf < 2; hf++) {
                float v0 = acc[ti][0][2*hf], v1 = acc[ti][0][2*hf+1];
                float v2 = acc[ti][1][2*hf], v3 = acc[ti][1][2*hf+1];
                float tmax = fmaxf(fmaxf(v0, v1), fmaxf(v2, v3));
                float nM = fmaxf(stM[ti][hf], tmax);
                float s = stS[ti][hf] * fexp(stM[ti][hf] - nM);
                s += fexp(v0-nM) + fexp(v1-nM) + fexp(v2-nM) + fexp(v3-nM);
                stM[ti][hf] = nM; stS[ti][hf] = s;
            }
        }
    }
    // butterfly over tg lanes, then across 8 warps
    #pragma unroll
    for (int ti = 0; ti < 4; ti++) {
        #pragma unroll
        for (int hf = 0; hf < 2; hf++) {
            float M = stM[ti][hf], Sm = stS[ti][hf];
            #pragma unroll
            for (int off = 1; off <= 2; off <<= 1) {
                float Mo = __shfl_xor_sync(0xffffffffu, M, off);
                float So = __shfl_xor_sync(0xffffffffu, Sm, off);
                float nM = fmaxf(M, Mo);
                Sm = Sm*fexp(M-nM) + So*fexp(Mo-nM);
                M = nM;
            }
            if (tg == 0) {
                int row = ti*16 + gq + 8*hf;
                Mred[row][warp] = M; Sred[row][warp] = Sm;
            }
        }
    }
    __syncthreads();
    if (t < 64) {
        float M = Mred[t][0], Sm = Sred[t][0];
        #pragma unroll
        for (int w = 1; w < 8; w++) {
            float Mo = Mred[t][w], So = Sred[t][w];
            float nM = fmaxf(M, Mo);
            Sm = Sm*fexp(M-nM) + So*fexp(Mo-nM);
            M = nM;
        }
        int idx = bh*NPTS + n0 + t;
        mxv[idx] = M;
        rsv[idx] = 1.f / Sm;
    }
}

// ------- mega dcomp (fp16 MMA): xr = v@P (full K) + colsum + d + t-GEMM + h ---
// One block per (64-m tile, bh). smem pool unions mainloop vs epilogue regions.
__global__ __launch_bounds__(256)
void k_dcomp_mega(const float* __restrict__ v, const float* __restrict__ S,
                  const float* __restrict__ mxv, const float* __restrict__ rsv,
                  const float* __restrict__ Wbase, float* __restrict__ h,
                  const float* __restrict__ tb, const float* __restrict__ bng,
                  const float* __restrict__ bnb, int l) {
    __shared__ uint32_t pool[9792];   // 39168 B
    #define VSM(c,n2)  pool[(c)*20 + (n2)]             // main: 0..1280
    #define PSM(n2,m)  pool[1280 + (n2)*72 + (m)]      // main: 1280..2432
    #define WSM(o,c)   (((float*)pool)[(o)*68 + (c)])          // epi: 0..4352
    #define DSM(c,m)   (((float*)pool)[4352 + (c)*68 + (m)])   // epi: 4352..8704
    #define RED(g,m)   (((float*)pool)[8704 + (g)*64 + (m)])   // epi: 8704..9728
    #define CSI(m)     (((float*)pool)[9728 + (m)])            // epi: 9728..9792
    int m0 = blockIdx.x * 64, bh = blockIdx.y, hh = bh & (NH-1);
    int t = threadIdx.x, warp = t >> 5, lane = t & 31;
    int wc = warp >> 2, wm = warp & 3;   // 2x4: each warp 32c x 16m
    int gq = lane >> 2, tg = lane & 3;
    const float* vb = v + (size_t)bh * HDIM * NPTS;
    const float* Sb = S + (size_t)bh * NPTS * NPTS;
    const float* mxb = mxv + bh*NPTS;
    const float* rsb = rsv + bh*NPTS;
    float* hb = h + (size_t)bh * HDIM * NPTS;
    float acc[2][2][4];
    #pragma unroll
    for (int i = 0; i < 2; i++)
        #pragma unroll
        for (int j = 0; j < 2; j++)
            #pragma unroll
            for (int c = 0; c < 4; c++) acc[i][j][c] = 0.f;
    float bsum[4] = {0.f, 0.f, 0.f, 0.f};
    int pr = t >> 4, pm4 = (t & 15) * 4;   // P-build assignment (fixed cols)

    for (int nc = 0; nc < NPTS; nc += 32) {
        __syncthreads();
        // V tile 64c x 32n -> half2 pairs along n
        #pragma unroll
        for (int r = 0; r < 2; r++) {
            int u = r*256 + t;
            int c = u >> 3, n4 = (u & 7) * 4;
            float4 vv = *(const float4*)&vb[(size_t)c*NPTS + nc + n4];
            uint2 w = {h2(vv.x, vv.y), h2(vv.z, vv.w)};
            *(uint2*)&VSM(c, n4 >> 1) = w;
        }
        // P tile: rows nc+2pr, nc+2pr+1 -> exp, colsum partials, pack half2
        {
            const float* S0 = &Sb[(size_t)(nc + 2*pr)*NPTS + m0 + pm4];
            float4 s0 = *(const float4*)S0;
            float4 s1 = *(const float4*)(S0 + NPTS);
            float mx0 = mxb[nc+2*pr],   rs0 = rsb[nc+2*pr];
            float mx1 = mxb[nc+2*pr+1], rs1 = rsb[nc+2*pr+1];
            float p00 = fexp(s0.x-mx0)*rs0, p01 = fexp(s0.y-mx0)*rs0;
            float p02 = fexp(s0.z-mx0)*rs0, p03 = fexp(s0.w-mx0)*rs0;
            float p10 = fexp(s1.x-mx1)*rs1, p11 = fexp(s1.y-mx1)*rs1;
            float p12 = fexp(s1.z-mx1)*rs1, p13 = fexp(s1.w-mx1)*rs1;
            bsum[0] += p00 + p10; bsum[1] += p01 + p11;
            bsum[2] += p02 + p12; bsum[3] += p03 + p13;
            uint4 w = {h2(p00,p10), h2(p01,p11), h2(p02,p12), h2(p03,p13)};
            *(uint4*)&PSM(pr, pm4) = w;
        }
        __syncthreads();
        // MMA: xr += V(64c x 32n) @ P(32n x 64m), 2 k16 steps
        #pragma unroll
        for (int nh = 0; nh < 16; nh += 8) {
            uint32_t a[2][4], b[2][2];
            #pragma unroll
            for (int ti = 0; ti < 2; ti++) {
                int cb = wc*32 + ti*16 + gq;
                a[ti][0] = VSM(cb,   nh+tg);
                a[ti][1] = VSM(cb+8, nh+tg);
                a[ti][2] = VSM(cb,   nh+4+tg);
                a[ti][3] = VSM(cb+8, nh+4+tg);
            }
            #pragma unroll
            for (int tj = 0; tj < 2; tj++) {
                int mb = wm*16 + tj*8 + gq;
                b[tj][0] = PSM(nh+tg,   mb);
                b[tj][1] = PSM(nh+4+tg, mb);
            }
            #pragma unroll
            for (int ti = 0; ti < 2; ti++)
                #pragma unroll
                for (int tj = 0; tj < 2; tj++)
                    MMA_F16(acc[ti][tj], a[ti], b[tj]);
        }
    }
    __syncthreads();   // main-loop smem free -> epilogue reuse
    // colsum partials -> RED; load t_w -> WSM (disjoint epi regions)
    #pragma unroll
    for (int j = 0; j < 4; j++) RED(pr, pm4 + j) = bsum[j];
    {
        const float* W = Wbase + (size_t)(l*NH + hh)*HDIM*HDIM;
        #pragma unroll
        for (int r = 0; r < 4; r++) {
            int u = r*1024 + t*4;
            int o = u >> 6, c4 = u & 63;
            *(float4*)&WSM(o, c4) = *(const float4*)&W[o*HDIM + c4];
        }
    }
    __syncthreads();
    if (t < 64) {
        float s = 0.f;
        #pragma unroll
        for (int g = 0; g < 16; g++) s += RED(g, t);
        CSI(t) = 1.f / (1e-9f + s);
    }
    __syncthreads();
    // d = h - xr * csinv  -> DSM
    #pragma unroll
    for (int ti = 0; ti < 2; ti++) {
        #pragma unroll
        for (int tj = 0; tj < 2; tj++) {
            int c = wc*32 + ti*16 + gq;
            int ml = wm*16 + tj*8 + 2*tg;
            float ci0 = CSI(ml), ci1 = CSI(ml+1);
            float2 h0 = *(const float2*)&hb[(size_t)c*NPTS + m0 + ml];
            float2 h1 = *(const float2*)&hb[(size_t)(c+8)*NPTS + m0 + ml];
            DSM(c,   ml)   = h0.x - acc[ti][tj][0]*ci0;
            DSM(c,   ml+1) = h0.y - acc[ti][tj][1]*ci1;
            DSM(c+8, ml)   = h1.x - acc[ti][tj][2]*ci0;
            DSM(c+8, ml+1) = h1.y - acc[ti][tj][3]*ci1;
        }
    }
    __syncthreads();
    // t-GEMM 64x64x64 + BN + relu + residual into h
    {
        int tx = t & 15, ty = t >> 4;
        float a2[4][4] = {};
        #pragma unroll
        for (int cc = 0; cc < 64; cc++) {
            float a[4];
            #pragma unroll
            for (int i = 0; i < 4; i++) a[i] = WSM(ty*4+i, cc);
            float4 bv = *(float4*)&DSM(cc, tx*4);
            float bb[4] = {bv.x, bv.y, bv.z, bv.w};
            #pragma unroll
            for (int i = 0; i < 4; i++)
                #pragma unroll
                for (int j = 0; j < 4; j++)
                    a2[i][j] = fmaf(a[i], bb[j], a2[i][j]);
        }
        int vbase = (l*NH + hh) * HDIM;
        #pragma unroll
        for (int i = 0; i < 4; i++) {
            int o = ty*4 + i;
            float alpha = bng[vbase+o] * rsqrtf(1.f + EPSBN);
            float beta  = tb[vbase+o]*alpha + bnb[vbase+o];
            float* p = &hb[(size_t)o*NPTS + m0 + tx*4];
            float4 hv = *(float4*)p;
            hv.x += fmaxf(fmaf(a2[i][0], alpha, beta), 0.f);
            hv.y += fmaxf(fmaf(a2[i][1], alpha, beta), 0.f);
            hv.z += fmaxf(fmaf(a2[i][2], alpha, beta), 0.f);
            hv.w += fmaxf(fmaf(a2[i][3], alpha, beta), 0.f);
            *(float4*)p = hv;
        }
    }
    #undef VSM
    #undef PSM
    #undef WSM
    #undef DSM
    #undef RED
    #undef CSI
}

// ---------------- host orchestration -------------------------------------------------
extern "C" void kernel_launch(void* const* d_in, const int* in_sizes, int n_in,
                              void* d_out, int out_size) {
    const float* x      = (const float*)d_in[0];
    const float* in_w1  = (const float*)d_in[1];
    const float* in_b1  = (const float*)d_in[2];
    const float* in_g1  = (const float*)d_in[3];
    const float* in_be1 = (const float*)d_in[4];
    const float* in_w2  = (const float*)d_in[5];
    const float* in_b2  = (const float*)d_in[6];
    const float* in_g2  = (const float*)d_in[7];
    const float* in_be2 = (const float*)d_in[8];
    const float* q_w    = (const float*)d_in[9];
    const float* k_w    = (const float*)d_in[10];
    const float* v_w    = (const float*)d_in[11];
    const float* v_b    = (const float*)d_in[12];
    const float* t_w    = (const float*)d_in[13];
    const float* t_b    = (const float*)d_in[14];
    const float* bn_g   = (const float*)d_in[15];
    const float* bn_b   = (const float*)d_in[16];
    const float* proj_w = (const float*)d_in[17];
    const float* proj_b = (const float*)d_in[18];

    float *hA, *hB, *qb, *kb, *vb, *Sb, *mxv, *rsv;
    cudaGetSymbolAddress((void**)&hA,  g_bufA);
    cudaGetSymbolAddress((void**)&hB,  g_bufB);
    cudaGetSymbolAddress((void**)&qb,  g_q);
    cudaGetSymbolAddress((void**)&kb,  g_k);
    cudaGetSymbolAddress((void**)&vb,  g_v);
    cudaGetSymbolAddress((void**)&Sb,  g_S);
    cudaGetSymbolAddress((void**)&mxv, g_mx);
    cudaGetSymbolAddress((void**)&rsv, g_rs);

    dim3 ttb(32, 8);
    k_transpose_in<<<dim3(NPTS/32, CCH/32, BNB), ttb>>>(x, hA);

    k_mlp<<<dim3(NPTS/64, CCH/64, BNB), 256>>>(in_w1, hA, hB, in_b1, in_g1, in_be1, 1);
    k_mlp<<<dim3(NPTS/64, CCH/64, BNB), 256>>>(in_w2, hB, hA, in_b2, in_g2, in_be2, 1);

    float* h = hA;
    float* o = hB;
    for (int l = 0; l < NL; l++) {
        k_qkv<<<dim3(NPTS/64, BHN), 256>>>(q_w, k_w, v_w, v_b, h, qb, kb, vb, l);
        k_scores_st<<<dim3(NPTS/64, BHN), 256>>>(qb, kb, Sb, mxv, rsv);
        k_dcomp_mega<<<dim3(NPTS/64, BHN), 256>>>(vb, Sb, mxv, rsv, t_w, h,
                                                  t_b, bn_g, bn_b, l);
        k_mlp<<<dim3(NPTS/64, CCH/64, BNB), 256>>>(proj_w + (size_t)l*CCH*CCH, h, o,
                                                   proj_b + (size_t)l*CCH,
                                                   nullptr, nullptr, 0);
        float* tmp = h; h = o; o = tmp;
    }

    k_transpose_out<<<dim3(CCH/32, NPTS/32, BNB), ttb>>>(h, (float*)d_out);
}

// round 10
// speedup vs baseline: 1.1962x; 1.1962x over previous
#include <cuda_runtime.h>
#include <cuda_fp16.h>
#include <math.h>
#include <stdint.h>

#define BNB  2
#define NPTS 2048
#define CCH  256
#define NH   4
#define HDIM 64
#define NL   4
#define BHN  (BNB*NH)
#define EPSBN 1e-5f

// ---------------- scratch (device globals; no allocation allowed) -------------
__device__ float g_bufA[BNB*CCH*NPTS];
__device__ float g_bufB[BNB*CCH*NPTS];
__device__ float g_q  [BHN*HDIM*NPTS];
__device__ float g_k  [BHN*HDIM*NPTS];
__device__ float g_v  [BHN*HDIM*NPTS];
__device__ float g_S  [(size_t)BHN*NPTS*NPTS];   // raw scores (mostly L2-resident)
__device__ float g_mx [BHN*NPTS];
__device__ float g_rs [BHN*NPTS];

// fast exp on the FMA pipe
__device__ __forceinline__ float fexp(float x) {
    x = fmaxf(x, -80.f);
    float t = fmaf(x, 1.44269504f, 12582912.f);
    int   e = __float_as_int(t) << 23;
    float r = t - 12582912.f;
    float f = fmaf(x, 1.44269504f, -r);
    float p = 1.54035304e-4f;
    p = fmaf(p, f, 1.33335581e-3f);
    p = fmaf(p, f, 9.61812911e-3f);
    p = fmaf(p, f, 5.55041087e-2f);
    p = fmaf(p, f, 2.40226507e-1f);
    p = fmaf(p, f, 6.93147181e-1f);
    p = fmaf(p, f, 1.0f);
    return __int_as_float(__float_as_int(p) + e);
}

__device__ __forceinline__ uint32_t h2(float a, float b) {
    __half2 h = __floats2half2_rn(a, b);
    return *reinterpret_cast<uint32_t*>(&h);
}

#define MMA_F16(c, a, b)                                                         \
    asm volatile("mma.sync.aligned.m16n8k16.row.col.f32.f16.f16.f32 "            \
                 "{%0,%1,%2,%3},{%4,%5,%6,%7},{%8,%9},{%0,%1,%2,%3};"            \
                 : "+f"((c)[0]), "+f"((c)[1]), "+f"((c)[2]), "+f"((c)[3])        \
                 : "r"((a)[0]), "r"((a)[1]), "r"((a)[2]), "r"((a)[3]),           \
                   "r"((b)[0]), "r"((b)[1]))

// ---------------- transposes ----------------
__global__ void k_transpose_in(const float* __restrict__ x, float* __restrict__ h) {
    __shared__ float tile[32][33];
    int b = blockIdx.z;
    int n0 = blockIdx.x * 32, c0 = blockIdx.y * 32;
    int tx = threadIdx.x, ty = threadIdx.y;
    for (int i = ty; i < 32; i += 8)
        tile[i][tx] = x[(size_t)b*NPTS*CCH + (size_t)(n0+i)*CCH + c0 + tx];
    __syncthreads();
    for (int i = ty; i < 32; i += 8)
        h[(size_t)b*CCH*NPTS + (size_t)(c0+i)*NPTS + n0 + tx] = tile[tx][i];
}

__global__ void k_transpose_out(const float* __restrict__ h, float* __restrict__ out) {
    __shared__ float tile[32][33];
    int b = blockIdx.z;
    int c0 = blockIdx.x * 32, n0 = blockIdx.y * 32;
    int tx = threadIdx.x, ty = threadIdx.y;
    for (int i = ty; i < 32; i += 8)
        tile[i][tx] = h[(size_t)b*CCH*NPTS + (size_t)(c0+i)*NPTS + n0 + tx];
    __syncthreads();
    for (int i = ty; i < 32; i += 8)
        out[(size_t)b*NPTS*CCH + (size_t)(n0+i)*CCH + c0 + tx] = tile[tx][i];
}

// ---------------- full-channel GEMM (MLP / proj), tile 64o x 128n, K step 16 ----
// (round-6 version: measured fastest config)
__global__ __launch_bounds__(256)
void k_mlp(const float* __restrict__ W, const float* __restrict__ in,
           float* __restrict__ out, const float* __restrict__ bvec,
           const float* __restrict__ gvec, const float* __restrict__ bevec,
           int relu) {
    __shared__ float As[64][16];
    __shared__ float Bs[16][128];
    int b  = blockIdx.z;
    int n0 = blockIdx.x * 128, o0 = blockIdx.y * 64;
    int t  = threadIdx.x, tx = t & 15, ty = t >> 4;
    const float* inb = in + (size_t)b*CCH*NPTS;
    int aoo = t >> 2, akk = (t & 3) * 4;
    float acc[4][8] = {};
    for (int kc = 0; kc < CCH; kc += 16) {
        *(float4*)&As[aoo][akk] = *(const float4*)&W[(size_t)(o0+aoo)*CCH + kc + akk];
        #pragma unroll
        for (int hf = 0; hf < 2; hf++) {
            int idx = hf*1024 + t*4;
            int kk = idx >> 7, nn = idx & 127;
            *(float4*)&Bs[kk][nn] = *(const float4*)&inb[(size_t)(kc+kk)*NPTS + n0 + nn];
        }
        __syncthreads();
        #pragma unroll
        for (int kk = 0; kk < 16; kk++) {
            float a[4];
            #pragma unroll
            for (int i = 0; i < 4; i++) a[i] = As[ty*4+i][kk];
            float4 b0 = *(float4*)&Bs[kk][tx*8];
            float4 b1 = *(float4*)&Bs[kk][tx*8+4];
            float bb[8] = {b0.x,b0.y,b0.z,b0.w,b1.x,b1.y,b1.z,b1.w};
            #pragma unroll
            for (int i = 0; i < 4; i++)
                #pragma unroll
                for (int j = 0; j < 8; j++)
                    acc[i][j] = fmaf(a[i], bb[j], acc[i][j]);
        }
        __syncthreads();
    }
    float* outb = out + (size_t)b*CCH*NPTS;
    #pragma unroll
    for (int i = 0; i < 4; i++) {
        int o = o0 + ty*4 + i;
        float alpha = 1.f, beta = 0.f;
        if (gvec) { alpha = gvec[o] * rsqrtf(1.f + EPSBN); beta = bvec[o]*alpha + bevec[o]; }
        else if (bvec) beta = bvec[o];
        float vv[8];
        #pragma unroll
        for (int j = 0; j < 8; j++) {
            vv[j] = fmaf(acc[i][j], alpha, beta);
            if (relu) vv[j] = fmaxf(vv[j], 0.f);
        }
        float4 s0 = {vv[0],vv[1],vv[2],vv[3]}, s1 = {vv[4],vv[5],vv[6],vv[7]};
        float* p = &outb[(size_t)o*NPTS + n0 + tx*8];
        *(float4*)p = s0; *(float4*)(p+4) = s1;
    }
}

// ------- fused q/k/v head GEMMs: one B-tile load, three weight passes ----------
// (round-6 version: 128n tile, measured 22.2us)
__global__ __launch_bounds__(256)
void k_qkv(const float* __restrict__ qw, const float* __restrict__ kw,
           const float* __restrict__ vw, const float* __restrict__ vbias,
           const float* __restrict__ in, float* __restrict__ qo,
           float* __restrict__ ko, float* __restrict__ vo, int l) {
    __shared__ float As[64][64];
    __shared__ float Bs[64][128];
    int n0 = blockIdx.x * 128, bh = blockIdx.y, hh = bh & (NH-1);
    int t = threadIdx.x, tx = t & 15, ty = t >> 4;
    const float* inb = in + (size_t)bh * HDIM * NPTS;
    int vbase = (l*NH + hh) * HDIM;
    #pragma unroll
    for (int r = 0; r < 8; r++) {
        int idx = r*1024 + t*4;
        int cc = idx >> 7, nn = idx & 127;
        *(float4*)&Bs[cc][nn] = *(const float4*)&inb[(size_t)cc*NPTS + n0 + nn];
    }
    for (int w = 0; w < 3; w++) {
        const float* W = (w == 0 ? qw : w == 1 ? kw : vw) + (size_t)(l*NH + hh)*HDIM*HDIM;
        __syncthreads();
        #pragma unroll
        for (int r = 0; r < 4; r++)
            ((float4*)As)[t + r*256] = ((const float4*)W)[t + r*256];
        __syncthreads();
        float acc[4][8] = {};
        #pragma unroll
        for (int cc = 0; cc < 64; cc++) {
            float a[4];
            #pragma unroll
            for (int i = 0; i < 4; i++) a[i] = As[ty*4+i][cc];
            float4 b0 = *(float4*)&Bs[cc][tx*8];
            float4 b1 = *(float4*)&Bs[cc][tx*8+4];
            float bb[8] = {b0.x,b0.y,b0.z,b0.w,b1.x,b1.y,b1.z,b1.w};
            #pragma unroll
            for (int i = 0; i < 4; i++)
                #pragma unroll
                for (int j = 0; j < 8; j++)
                    acc[i][j] = fmaf(a[i], bb[j], acc[i][j]);
        }
        float* outb = (w == 0 ? qo : w == 1 ? ko : vo) + (size_t)bh * HDIM * NPTS;
        #pragma unroll
        for (int i = 0; i < 4; i++) {
            int o = ty*4 + i;
            float bb = (w == 2) ? vbias[vbase + o] : 0.f;
            float4 s0 = {acc[i][0]+bb, acc[i][1]+bb, acc[i][2]+bb, acc[i][3]+bb};
            float4 s1 = {acc[i][4]+bb, acc[i][5]+bb, acc[i][6]+bb, acc[i][7]+bb};
            float* p = &outb[(size_t)o*NPTS + n0 + tx*8];
            *(float4*)p = s0; *(float4*)(p+4) = s1;
        }
    }
}

// ---- scores + online row stats, fp16 MMA: block = 64 n-rows x full m sweep ----
// m-chunk 256: warp tile 64n x 32m (ti=4, tj=4); fewer barriers, better LDS/MMA.
__global__ __launch_bounds__(256)
void k_scores_st(const float* __restrict__ q, const float* __restrict__ k,
                 float* __restrict__ S, float* __restrict__ mxv,
                 float* __restrict__ rsv) {
    __shared__ uint32_t Qh[32][72];    // [o2][n]  72%32==8 -> conflict-free frags
    __shared__ uint32_t Kh[32][264];   // [o2][m]  264%32==8
    __shared__ float Mred[64][8], Sred[64][8];
    int n0 = blockIdx.x * 64, bh = blockIdx.y;
    const float* qb = q + (size_t)bh * HDIM * NPTS;
    const float* kb = k + (size_t)bh * HDIM * NPTS;
    int t = threadIdx.x, warp = t >> 5, lane = t & 31;
    int gq = lane >> 2, tg = lane & 3;
    // persistent Q tile: 64o x 64n, packed pairs (2rr, 2rr+1) along o
    #pragma unroll
    for (int r = 0; r < 2; r++) {
        int u = r*256 + t;
        int rr = u >> 4, n4 = (u & 15) * 4;
        float4 q0 = *(const float4*)&qb[(size_t)(2*rr)*NPTS + n0 + n4];
        float4 q1 = *(const float4*)&qb[(size_t)(2*rr+1)*NPTS + n0 + n4];
        uint4 w = {h2(q0.x,q1.x), h2(q0.y,q1.y), h2(q0.z,q1.z), h2(q0.w,q1.w)};
        *(uint4*)&Qh[rr][n4] = w;
    }
    float stM[4][2], stS[4][2];
    #pragma unroll
    for (int i = 0; i < 4; i++)
        #pragma unroll
        for (int hf = 0; hf < 2; hf++) { stM[i][hf] = -1e30f; stS[i][hf] = 0.f; }
    float* Sb = S + (size_t)bh * NPTS * NPTS;

    for (int m0 = 0; m0 < NPTS; m0 += 256) {
        __syncthreads();
        // K panel 64o x 256m -> half2 pairs along o
        #pragma unroll
        for (int r = 0; r < 8; r++) {
            int u = r*256 + t;
            int rr = u >> 6, m4 = (u & 63) * 4;
            float4 k0 = *(const float4*)&kb[(size_t)(2*rr)*NPTS + m0 + m4];
            float4 k1 = *(const float4*)&kb[(size_t)(2*rr+1)*NPTS + m0 + m4];
            uint4 w = {h2(k0.x,k1.x), h2(k0.y,k1.y), h2(k0.z,k1.z), h2(k0.w,k1.w)};
            *(uint4*)&Kh[rr][m4] = w;
        }
        __syncthreads();
        float acc[4][4][4];
        #pragma unroll
        for (int i = 0; i < 4; i++)
            #pragma unroll
            for (int j = 0; j < 4; j++)
                #pragma unroll
                for (int c = 0; c < 4; c++) acc[i][j][c] = 0.f;
        #pragma unroll
        for (int kh = 0; kh < 32; kh += 8) {    // 4 x k16 steps over K=64
            uint32_t a[4][4], b[4][2];
            #pragma unroll
            for (int ti = 0; ti < 4; ti++) {
                int nb = ti*16 + gq;
                a[ti][0] = Qh[kh+tg][nb];
                a[ti][1] = Qh[kh+tg][nb+8];
                a[ti][2] = Qh[kh+4+tg][nb];
                a[ti][3] = Qh[kh+4+tg][nb+8];
            }
            #pragma unroll
            for (int tj = 0; tj < 4; tj++) {
                int mb = warp*32 + tj*8 + gq;
                b[tj][0] = Kh[kh+tg][mb];
                b[tj][1] = Kh[kh+4+tg][mb];
            }
            #pragma unroll
            for (int ti = 0; ti < 4; ti++)
                #pragma unroll
                for (int tj = 0; tj < 4; tj++)
                    MMA_F16(acc[ti][tj], a[ti], b[tj]);
        }
        // store raw S + online stats
        #pragma unroll
        for (int ti = 0; ti < 4; ti++) {
            #pragma unroll
            for (int tj = 0; tj < 4; tj++) {
                int n = n0 + ti*16 + gq;
                int m = m0 + warp*32 + tj*8 + 2*tg;
                float2 lo = {acc[ti][tj][0], acc[ti][tj][1]};
                float2 hi = {acc[ti][tj][2], acc[ti][tj][3]};
                *(float2*)&Sb[(size_t)n*NPTS + m]     = lo;
                *(float2*)&Sb[(size_t)(n+8)*NPTS + m] = hi;
            }
            #pragma unroll
            for (int hf = 0; hf < 2; hf++) {
                float tmax = stM[ti][hf];
                #pragma unroll
                for (int tj = 0; tj < 4; tj++)
                    tmax = fmaxf(tmax, fmaxf(acc[ti][tj][2*hf], acc[ti][tj][2*hf+1]));
                float s = stS[ti][hf] * fexp(stM[ti][hf] - tmax);
                #pragma unroll
                for (int tj = 0; tj < 4; tj++)
                    s += fexp(acc[ti][tj][2*hf]-tmax) + fexp(acc[ti][tj][2*hf+1]-tmax);
                stM[ti][hf] = tmax; stS[ti][hf] = s;
            }
        }
    }
    // butterfly over tg lanes, then across 8 warps
    #pragma unroll
    for (int ti = 0; ti < 4; ti++) {
        #pragma unroll
        for (int hf = 0; hf < 2; hf++) {
            float M = stM[ti][hf], Sm = stS[ti][hf];
            #pragma unroll
            for (int off = 1; off <= 2; off <<= 1) {
                float Mo = __shfl_xor_sync(0xffffffffu, M, off);
                float So = __shfl_xor_sync(0xffffffffu, Sm, off);
                float nM = fmaxf(M, Mo);
                Sm = Sm*fexp(M-nM) + So*fexp(Mo-nM);
                M = nM;
            }
            if (tg == 0) {
                int row = ti*16 + gq + 8*hf;
                Mred[row][warp] = M; Sred[row][warp] = Sm;
            }
        }
    }
    __syncthreads();
    if (t < 64) {
        float M = Mred[t][0], Sm = Sred[t][0];
        #pragma unroll
        for (int w = 1; w < 8; w++) {
            float Mo = Mred[t][w], So = Sred[t][w];
            float nM = fmaxf(M, Mo);
            Sm = Sm*fexp(M-nM) + So*fexp(Mo-nM);
            M = nM;
        }
        int idx = bh*NPTS + n0 + t;
        mxv[idx] = M;
        rsv[idx] = 1.f / Sm;
    }
}

// ------- mega dcomp (fp16 MMA): xr = v@P (full K) + colsum + d + t-GEMM + h ---
// n-chunk 64 (4 k16 steps per barrier pair). One block per (64-m tile, bh).
__global__ __launch_bounds__(256)
void k_dcomp_mega(const float* __restrict__ v, const float* __restrict__ S,
                  const float* __restrict__ mxv, const float* __restrict__ rsv,
                  const float* __restrict__ Wbase, float* __restrict__ h,
                  const float* __restrict__ tb, const float* __restrict__ bng,
                  const float* __restrict__ bnb, int l) {
    __shared__ uint32_t pool[9792];   // 39168 B
    #define VSM(c,n2)  pool[(c)*36 + (n2)]             // main: 0..2304
    #define PSM(n2,m)  pool[2304 + (n2)*72 + (m)]      // main: 2304..4608
    #define WSM(o,c)   (((float*)pool)[(o)*68 + (c)])          // epi: 0..4352
    #define DSM(c,m)   (((float*)pool)[4352 + (c)*68 + (m)])   // epi: 4352..8704
    #define RED(g,m)   (((float*)pool)[8704 + (g)*64 + (m)])   // epi: 8704..9728
    #define CSI(m)     (((float*)pool)[9728 + (m)])            // epi: 9728..9792
    int m0 = blockIdx.x * 64, bh = blockIdx.y, hh = bh & (NH-1);
    int t = threadIdx.x, warp = t >> 5, lane = t & 31;
    int wc = warp >> 2, wm = warp & 3;   // 2x4: each warp 32c x 16m
    int gq = lane >> 2, tg = lane & 3;
    const float* vb = v + (size_t)bh * HDIM * NPTS;
    const float* Sb = S + (size_t)bh * NPTS * NPTS;
    const float* mxb = mxv + bh*NPTS;
    const float* rsb = rsv + bh*NPTS;
    float* hb = h + (size_t)bh * HDIM * NPTS;
    float acc[2][2][4];
    #pragma unroll
    for (int i = 0; i < 2; i++)
        #pragma unroll
        for (int j = 0; j < 2; j++)
            #pragma unroll
            for (int c = 0; c < 4; c++) acc[i][j][c] = 0.f;
    float bsum[4] = {0.f, 0.f, 0.f, 0.f};
    int pr = t >> 4, pm4 = (t & 15) * 4;   // P-build: 4 rows x 4 fixed cols

    for (int nc = 0; nc < NPTS; nc += 64) {
        __syncthreads();
        // V tile 64c x 64n -> half2 pairs along n
        #pragma unroll
        for (int r = 0; r < 4; r++) {
            int u = r*256 + t;
            int c = u >> 4, pos = u & 15;          // pos*4 = n offset
            float4 vv = *(const float4*)&vb[(size_t)c*NPTS + nc + pos*4];
            uint2 w = {h2(vv.x, vv.y), h2(vv.z, vv.w)};
            *(uint2*)&VSM(c, pos*2) = w;
        }
        // P tile: rows nc+4pr..+3, cols pm4..+3 -> exp, colsum, pack half2
        {
            const float* S0 = &Sb[(size_t)(nc + 4*pr)*NPTS + m0 + pm4];
            float4 s0 = *(const float4*)S0;
            float4 s1 = *(const float4*)(S0 + NPTS);
            float4 s2 = *(const float4*)(S0 + 2*NPTS);
            float4 s3 = *(const float4*)(S0 + 3*NPTS);
            float mx0 = mxb[nc+4*pr],   rs0 = rsb[nc+4*pr];
            float mx1 = mxb[nc+4*pr+1], rs1 = rsb[nc+4*pr+1];
            float mx2 = mxb[nc+4*pr+2], rs2 = rsb[nc+4*pr+2];
            float mx3 = mxb[nc+4*pr+3], rs3 = rsb[nc+4*pr+3];
            float p00 = fexp(s0.x-mx0)*rs0, p01 = fexp(s0.y-mx0)*rs0;
            float p02 = fexp(s0.z-mx0)*rs0, p03 = fexp(s0.w-mx0)*rs0;
            float p10 = fexp(s1.x-mx1)*rs1, p11 = fexp(s1.y-mx1)*rs1;
            float p12 = fexp(s1.z-mx1)*rs1, p13 = fexp(s1.w-mx1)*rs1;
            float p20 = fexp(s2.x-mx2)*rs2, p21 = fexp(s2.y-mx2)*rs2;
            float p22 = fexp(s2.z-mx2)*rs2, p23 = fexp(s2.w-mx2)*rs2;
            float p30 = fexp(s3.x-mx3)*rs3, p31 = fexp(s3.y-mx3)*rs3;
            float p32 = fexp(s3.z-mx3)*rs3, p33 = fexp(s3.w-mx3)*rs3;
            bsum[0] += p00 + p10 + p20 + p30;
            bsum[1] += p01 + p11 + p21 + p31;
            bsum[2] += p02 + p12 + p22 + p32;
            bsum[3] += p03 + p13 + p23 + p33;
            uint4 w0 = {h2(p00,p10), h2(p01,p11), h2(p02,p12), h2(p03,p13)};
            uint4 w1 = {h2(p20,p30), h2(p21,p31), h2(p22,p32), h2(p23,p33)};
            *(uint4*)&PSM(2*pr,   pm4) = w0;
            *(uint4*)&PSM(2*pr+1, pm4) = w1;
        }
        __syncthreads();
        // MMA: xr += V(64c x 64n) @ P(64n x 64m), 4 k16 steps
        #pragma unroll
        for (int nh = 0; nh < 32; nh += 8) {
            uint32_t a[2][4], b[2][2];
            #pragma unroll
            for (int ti = 0; ti < 2; ti++) {
                int cb = wc*32 + ti*16 + gq;
                a[ti][0] = VSM(cb,   nh+tg);
                a[ti][1] = VSM(cb+8, nh+tg);
                a[ti][2] = VSM(cb,   nh+4+tg);
                a[ti][3] = VSM(cb+8, nh+4+tg);
            }
            #pragma unroll
            for (int tj = 0; tj < 2; tj++) {
                int mb = wm*16 + tj*8 + gq;
                b[tj][0] = PSM(nh+tg,   mb);
                b[tj][1] = PSM(nh+4+tg, mb);
            }
            #pragma unroll
            for (int ti = 0; ti < 2; ti++)
                #pragma unroll
                for (int tj = 0; tj < 2; tj++)
                    MMA_F16(acc[ti][tj], a[ti], b[tj]);
        }
    }
    __syncthreads();   // main-loop smem free -> epilogue reuse
    // colsum partials -> RED; load t_w -> WSM (disjoint epi regions)
    #pragma unroll
    for (int j = 0; j < 4; j++) RED(pr, pm4 + j) = bsum[j];
    {
        const float* W = Wbase + (size_t)(l*NH + hh)*HDIM*HDIM;
        #pragma unroll
        for (int r = 0; r < 4; r++) {
            int u = r*1024 + t*4;
            int o = u >> 6, c4 = u & 63;
            *(float4*)&WSM(o, c4) = *(const float4*)&W[o*HDIM + c4];
        }
    }
    __syncthreads();
    if (t < 64) {
        float s = 0.f;
        #pragma unroll
        for (int g = 0; g < 16; g++) s += RED(g, t);
        CSI(t) = 1.f / (1e-9f + s);
    }
    __syncthreads();
    // d = h - xr * csinv  -> DSM
    #pragma unroll
    for (int ti = 0; ti < 2; ti++) {
        #pragma unroll
        for (int tj = 0; tj < 2; tj++) {
            int c = wc*32 + ti*16 + gq;
            int ml = wm*16 + tj*8 + 2*tg;
            float ci0 = CSI(ml), ci1 = CSI(ml+1);
            float2 h0 = *(const float2*)&hb[(size_t)c*NPTS + m0 + ml];
            float2 h1 = *(const float2*)&hb[(size_t)(c+8)*NPTS + m0 + ml];
            DSM(c,   ml)   = h0.x - acc[ti][tj][0]*ci0;
            DSM(c,   ml+1) = h0.y - acc[ti][tj][1]*ci1;
            DSM(c+8, ml)   = h1.x - acc[ti][tj][2]*ci0;
            DSM(c+8, ml+1) = h1.y - acc[ti][tj][3]*ci1;
        }
    }
    __syncthreads();
    // t-GEMM 64x64x64 + BN + relu + residual into h
    {
        int tx = t & 15, ty = t >> 4;
        float a2[4][4] = {};
        #pragma unroll
        for (int cc = 0; cc < 64; cc++) {
            float a[4];
            #pragma unroll
            for (int i = 0; i < 4; i++) a[i] = WSM(ty*4+i, cc);
            float4 bv = *(float4*)&DSM(cc, tx*4);
            float bb[4] = {bv.x, bv.y, bv.z, bv.w};
            #pragma unroll
            for (int i = 0; i < 4; i++)
                #pragma unroll
                for (int j = 0; j < 4; j++)
                    a2[i][j] = fmaf(a[i], bb[j], a2[i][j]);
        }
        int vbase = (l*NH + hh) * HDIM;
        #pragma unroll
        for (int i = 0; i < 4; i++) {
            int o = ty*4 + i;
            float alpha = bng[vbase+o] * rsqrtf(1.f + EPSBN);
            float beta  = tb[vbase+o]*alpha + bnb[vbase+o];
            float* p = &hb[(size_t)o*NPTS + m0 + tx*4];
            float4 hv = *(float4*)p;
            hv.x += fmaxf(fmaf(a2[i][0], alpha, beta), 0.f);
            hv.y += fmaxf(fmaf(a2[i][1], alpha, beta), 0.f);
            hv.z += fmaxf(fmaf(a2[i][2], alpha, beta), 0.f);
            hv.w += fmaxf(fmaf(a2[i][3], alpha, beta), 0.f);
            *(float4*)p = hv;
        }
    }
    #undef VSM
    #undef PSM
    #undef WSM
    #undef DSM
    #undef RED
    #undef CSI
}

// ---------------- host orchestration -------------------------------------------------
extern "C" void kernel_launch(void* const* d_in, const int* in_sizes, int n_in,
                              void* d_out, int out_size) {
    const float* x      = (const float*)d_in[0];
    const float* in_w1  = (const float*)d_in[1];
    const float* in_b1  = (const float*)d_in[2];
    const float* in_g1  = (const float*)d_in[3];
    const float* in_be1 = (const float*)d_in[4];
    const float* in_w2  = (const float*)d_in[5];
    const float* in_b2  = (const float*)d_in[6];
    const float* in_g2  = (const float*)d_in[7];
    const float* in_be2 = (const float*)d_in[8];
    const float* q_w    = (const float*)d_in[9];
    const float* k_w    = (const float*)d_in[10];
    const float* v_w    = (const float*)d_in[11];
    const float* v_b    = (const float*)d_in[12];
    const float* t_w    = (const float*)d_in[13];
    const float* t_b    = (const float*)d_in[14];
    const float* bn_g   = (const float*)d_in[15];
    const float* bn_b   = (const float*)d_in[16];
    const float* proj_w = (const float*)d_in[17];
    const float* proj_b = (const float*)d_in[18];

    float *hA, *hB, *qb, *kb, *vb, *Sb, *mxv, *rsv;
    cudaGetSymbolAddress((void**)&hA,  g_bufA);
    cudaGetSymbolAddress((void**)&hB,  g_bufB);
    cudaGetSymbolAddress((void**)&qb,  g_q);
    cudaGetSymbolAddress((void**)&kb,  g_k);
    cudaGetSymbolAddress((void**)&vb,  g_v);
    cudaGetSymbolAddress((void**)&Sb,  g_S);
    cudaGetSymbolAddress((void**)&mxv, g_mx);
    cudaGetSymbolAddress((void**)&rsv, g_rs);

    dim3 ttb(32, 8);
    k_transpose_in<<<dim3(NPTS/32, CCH/32, BNB), ttb>>>(x, hA);

    k_mlp<<<dim3(NPTS/128, CCH/64, BNB), 256>>>(in_w1, hA, hB, in_b1, in_g1, in_be1, 1);
    k_mlp<<<dim3(NPTS/128, CCH/64, BNB), 256>>>(in_w2, hB, hA, in_b2, in_g2, in_be2, 1);

    float* h = hA;
    float* o = hB;
    for (int l = 0; l < NL; l++) {
        k_qkv<<<dim3(NPTS/128, BHN), 256>>>(q_w, k_w, v_w, v_b, h, qb, kb, vb, l);
        k_scores_st<<<dim3(NPTS/64, BHN), 256>>>(qb, kb, Sb, mxv, rsv);
        k_dcomp_mega<<<dim3(NPTS/64, BHN), 256>>>(vb, Sb, mxv, rsv, t_w, h,
                                                  t_b, bn_g, bn_b, l);
        k_mlp<<<dim3(NPTS/128, CCH/64, BNB), 256>>>(proj_w + (size_t)l*CCH*CCH, h, o,
                                                    proj_b + (size_t)l*CCH,
                                                    nullptr, nullptr, 0);
        float* tmp = h; h = o; o = tmp;
    }

    k_transpose_out<<<dim3(CCH/32, NPTS/32, BNB), ttb>>>(h, (float*)d_out);
}

// round 11
// speedup vs baseline: 1.7719x; 1.4813x over previous
#include <cuda_runtime.h>
#include <cuda_fp16.h>
#include <math.h>
#include <stdint.h>

#define BNB  2
#define NPTS 2048
#define CCH  256
#define NH   4
#define HDIM 64
#define NL   4
#define BHN  (BNB*NH)
#define EPSBN 1e-5f

// ---------------- scratch (device globals; no allocation allowed) -------------
__device__ float    g_bufA[BNB*CCH*NPTS];
__device__ float    g_bufB[BNB*CCH*NPTS];
__device__ uint32_t g_qh[BHN*32*NPTS];        // q packed half2 along o: [bh][o2][n]
__device__ uint32_t g_kh[BHN*32*NPTS];        // k packed half2 along o: [bh][o2][m]
__device__ uint32_t g_vh[BHN*64*(NPTS/2)];    // v packed half2 along n: [bh][c][n2]
__device__ __half   g_Sh[(size_t)BHN*NPTS*NPTS];  // raw scores fp16 (67MB, L2-resident)
__device__ float    g_mx[BHN*NPTS];
__device__ float    g_rs[BHN*NPTS];

// fast exp on the FMA pipe
__device__ __forceinline__ float fexp(float x) {
    x = fmaxf(x, -80.f);
    float t = fmaf(x, 1.44269504f, 12582912.f);
    int   e = __float_as_int(t) << 23;
    float r = t - 12582912.f;
    float f = fmaf(x, 1.44269504f, -r);
    float p = 1.54035304e-4f;
    p = fmaf(p, f, 1.33335581e-3f);
    p = fmaf(p, f, 9.61812911e-3f);
    p = fmaf(p, f, 5.55041087e-2f);
    p = fmaf(p, f, 2.40226507e-1f);
    p = fmaf(p, f, 6.93147181e-1f);
    p = fmaf(p, f, 1.0f);
    return __int_as_float(__float_as_int(p) + e);
}

__device__ __forceinline__ uint32_t h2(float a, float b) {
    __half2 h = __floats2half2_rn(a, b);
    return *reinterpret_cast<uint32_t*>(&h);
}
__device__ __forceinline__ float2 h2f(uint32_t u) {
    return __half22float2(*reinterpret_cast<__half2*>(&u));
}

#define MMA_F16(c, a, b)                                                         \
    asm volatile("mma.sync.aligned.m16n8k16.row.col.f32.f16.f16.f32 "            \
                 "{%0,%1,%2,%3},{%4,%5,%6,%7},{%8,%9},{%0,%1,%2,%3};"            \
                 : "+f"((c)[0]), "+f"((c)[1]), "+f"((c)[2]), "+f"((c)[3])        \
                 : "r"((a)[0]), "r"((a)[1]), "r"((a)[2]), "r"((a)[3]),           \
                   "r"((b)[0]), "r"((b)[1]))

// ---------------- transposes ----------------
__global__ void k_transpose_in(const float* __restrict__ x, float* __restrict__ h) {
    __shared__ float tile[32][33];
    int b = blockIdx.z;
    int n0 = blockIdx.x * 32, c0 = blockIdx.y * 32;
    int tx = threadIdx.x, ty = threadIdx.y;
    for (int i = ty; i < 32; i += 8)
        tile[i][tx] = x[(size_t)b*NPTS*CCH + (size_t)(n0+i)*CCH + c0 + tx];
    __syncthreads();
    for (int i = ty; i < 32; i += 8)
        h[(size_t)b*CCH*NPTS + (size_t)(c0+i)*NPTS + n0 + tx] = tile[tx][i];
}

__global__ void k_transpose_out(const float* __restrict__ h, float* __restrict__ out) {
    __shared__ float tile[32][33];
    int b = blockIdx.z;
    int c0 = blockIdx.x * 32, n0 = blockIdx.y * 32;
    int tx = threadIdx.x, ty = threadIdx.y;
    for (int i = ty; i < 32; i += 8)
        tile[i][tx] = h[(size_t)b*CCH*NPTS + (size_t)(c0+i)*NPTS + n0 + tx];
    __syncthreads();
    for (int i = ty; i < 32; i += 8)
        out[(size_t)b*NPTS*CCH + (size_t)(n0+i)*CCH + c0 + tx] = tile[tx][i];
}

// ---------------- full-channel GEMM (MLP / proj), tile 64o x 128n ----------------
__global__ __launch_bounds__(256)
void k_mlp(const float* __restrict__ W, const float* __restrict__ in,
           float* __restrict__ out, const float* __restrict__ bvec,
           const float* __restrict__ gvec, const float* __restrict__ bevec,
           int relu) {
    __shared__ float As[64][16];
    __shared__ float Bs[16][128];
    int b  = blockIdx.z;
    int n0 = blockIdx.x * 128, o0 = blockIdx.y * 64;
    int t  = threadIdx.x, tx = t & 15, ty = t >> 4;
    const float* inb = in + (size_t)b*CCH*NPTS;
    int aoo = t >> 2, akk = (t & 3) * 4;
    float acc[4][8] = {};
    for (int kc = 0; kc < CCH; kc += 16) {
        *(float4*)&As[aoo][akk] = *(const float4*)&W[(size_t)(o0+aoo)*CCH + kc + akk];
        #pragma unroll
        for (int hf = 0; hf < 2; hf++) {
            int idx = hf*1024 + t*4;
            int kk = idx >> 7, nn = idx & 127;
            *(float4*)&Bs[kk][nn] = *(const float4*)&inb[(size_t)(kc+kk)*NPTS + n0 + nn];
        }
        __syncthreads();
        #pragma unroll
        for (int kk = 0; kk < 16; kk++) {
            float a[4];
            #pragma unroll
            for (int i = 0; i < 4; i++) a[i] = As[ty*4+i][kk];
            float4 b0 = *(float4*)&Bs[kk][tx*8];
            float4 b1 = *(float4*)&Bs[kk][tx*8+4];
            float bb[8] = {b0.x,b0.y,b0.z,b0.w,b1.x,b1.y,b1.z,b1.w};
            #pragma unroll
            for (int i = 0; i < 4; i++)
                #pragma unroll
                for (int j = 0; j < 8; j++)
                    acc[i][j] = fmaf(a[i], bb[j], acc[i][j]);
        }
        __syncthreads();
    }
    float* outb = out + (size_t)b*CCH*NPTS;
    #pragma unroll
    for (int i = 0; i < 4; i++) {
        int o = o0 + ty*4 + i;
        float alpha = 1.f, beta = 0.f;
        if (gvec) { alpha = gvec[o] * rsqrtf(1.f + EPSBN); beta = bvec[o]*alpha + bevec[o]; }
        else if (bvec) beta = bvec[o];
        float vv[8];
        #pragma unroll
        for (int j = 0; j < 8; j++) {
            vv[j] = fmaf(acc[i][j], alpha, beta);
            if (relu) vv[j] = fmaxf(vv[j], 0.f);
        }
        float4 s0 = {vv[0],vv[1],vv[2],vv[3]}, s1 = {vv[4],vv[5],vv[6],vv[7]};
        float* p = &outb[(size_t)o*NPTS + n0 + tx*8];
        *(float4*)p = s0; *(float4*)(p+4) = s1;
    }
}

// ------- fused q/k/v head GEMMs: fp32 compute, half2-packed outputs -----------
// q,k: [o2=32][n] packed along o. v: [c=64][n2] packed along n.
__global__ __launch_bounds__(256)
void k_qkv(const float* __restrict__ qw, const float* __restrict__ kw,
           const float* __restrict__ vw, const float* __restrict__ vbias,
           const float* __restrict__ in, uint32_t* __restrict__ qo,
           uint32_t* __restrict__ ko, uint32_t* __restrict__ vo, int l) {
    __shared__ float As[64][64];
    __shared__ float Bs[64][128];
    int n0 = blockIdx.x * 128, bh = blockIdx.y, hh = bh & (NH-1);
    int t = threadIdx.x, tx = t & 15, ty = t >> 4;
    const float* inb = in + (size_t)bh * HDIM * NPTS;
    int vbase = (l*NH + hh) * HDIM;
    #pragma unroll
    for (int r = 0; r < 8; r++) {
        int idx = r*1024 + t*4;
        int cc = idx >> 7, nn = idx & 127;
        *(float4*)&Bs[cc][nn] = *(const float4*)&inb[(size_t)cc*NPTS + n0 + nn];
    }
    for (int w = 0; w < 3; w++) {
        const float* W = (w == 0 ? qw : w == 1 ? kw : vw) + (size_t)(l*NH + hh)*HDIM*HDIM;
        __syncthreads();
        #pragma unroll
        for (int r = 0; r < 4; r++)
            ((float4*)As)[t + r*256] = ((const float4*)W)[t + r*256];
        __syncthreads();
        float acc[4][8] = {};
        #pragma unroll
        for (int cc = 0; cc < 64; cc++) {
            float a[4];
            #pragma unroll
            for (int i = 0; i < 4; i++) a[i] = As[ty*4+i][cc];
            float4 b0 = *(float4*)&Bs[cc][tx*8];
            float4 b1 = *(float4*)&Bs[cc][tx*8+4];
            float bb[8] = {b0.x,b0.y,b0.z,b0.w,b1.x,b1.y,b1.z,b1.w};
            #pragma unroll
            for (int i = 0; i < 4; i++)
                #pragma unroll
                for (int j = 0; j < 8; j++)
                    acc[i][j] = fmaf(a[i], bb[j], acc[i][j]);
        }
        if (w < 2) {
            uint32_t* outb = (w == 0 ? qo : ko) + (size_t)bh * 32 * NPTS;
            // o-pairs: rows (4ty,4ty+1) -> o2=2ty ; rows (4ty+2,4ty+3) -> o2=2ty+1
            #pragma unroll
            for (int pp = 0; pp < 2; pp++) {
                int i0 = pp*2;
                uint4 u0 = {h2(acc[i0][0],acc[i0+1][0]), h2(acc[i0][1],acc[i0+1][1]),
                            h2(acc[i0][2],acc[i0+1][2]), h2(acc[i0][3],acc[i0+1][3])};
                uint4 u1 = {h2(acc[i0][4],acc[i0+1][4]), h2(acc[i0][5],acc[i0+1][5]),
                            h2(acc[i0][6],acc[i0+1][6]), h2(acc[i0][7],acc[i0+1][7])};
                uint32_t* p = &outb[(size_t)(ty*2+pp)*NPTS + n0 + tx*8];
                *(uint4*)p = u0; *(uint4*)(p+4) = u1;
            }
        } else {
            uint32_t* outb = vo + (size_t)bh * 64 * (NPTS/2);
            #pragma unroll
            for (int i = 0; i < 4; i++) {
                float bb = vbias[vbase + ty*4 + i];
                uint4 u = {h2(acc[i][0]+bb, acc[i][1]+bb), h2(acc[i][2]+bb, acc[i][3]+bb),
                           h2(acc[i][4]+bb, acc[i][5]+bb), h2(acc[i][6]+bb, acc[i][7]+bb)};
                *(uint4*)&outb[(size_t)(ty*4+i)*(NPTS/2) + ((n0 + tx*8) >> 1)] = u;
            }
        }
    }
}

// ---- scores + online row stats, fp16 MMA, prefetched K chunks ----------------
// block = 64 n-rows x full m sweep (chunks of 128). S stored as half.
// Stats computed on the QUANTIZED (stored) values for consistency with dcomp.
__global__ __launch_bounds__(256)
void k_scores_st(const uint32_t* __restrict__ q, const uint32_t* __restrict__ k,
                 __half* __restrict__ S, float* __restrict__ mxv,
                 float* __restrict__ rsv) {
    __shared__ uint32_t Qh[32][72];    // [o2][n]
    __shared__ uint32_t Kh[32][136];   // [o2][m]
    __shared__ float Mred[64][8], Sred[64][8];
    int n0 = blockIdx.x * 64, bh = blockIdx.y;
    const uint32_t* qb = q + (size_t)bh * 32 * NPTS;
    const uint32_t* kb = k + (size_t)bh * 32 * NPTS;
    uint32_t* Su = (uint32_t*)(S + (size_t)bh * NPTS * NPTS);
    int t = threadIdx.x, warp = t >> 5, lane = t & 31;
    int gq = lane >> 2, tg = lane & 3;
    // persistent Q tile 32o2 x 64n
    #pragma unroll
    for (int r = 0; r < 2; r++) {
        int u = r*256 + t;
        int rr = u >> 4, n4 = (u & 15) * 4;
        *(uint4*)&Qh[rr][n4] = *(const uint4*)&qb[(size_t)rr*NPTS + n0 + n4];
    }
    float stM[4][2], stS[4][2];
    #pragma unroll
    for (int i = 0; i < 4; i++)
        #pragma unroll
        for (int hf = 0; hf < 2; hf++) { stM[i][hf] = -1e30f; stS[i][hf] = 0.f; }
    // prefetch K chunk 0
    uint4 kr[4];
    #pragma unroll
    for (int r = 0; r < 4; r++) {
        int u = r*256 + t;
        int rr = u >> 5, m4 = (u & 31) * 4;
        kr[r] = *(const uint4*)&kb[(size_t)rr*NPTS + m4];
    }
    for (int m0 = 0; m0 < NPTS; m0 += 128) {
        __syncthreads();                  // prev MMA done reading Kh
        #pragma unroll
        for (int r = 0; r < 4; r++) {
            int u = r*256 + t;
            int rr = u >> 5, m4 = (u & 31) * 4;
            *(uint4*)&Kh[rr][m4] = kr[r];
        }
        if (m0 + 128 < NPTS) {            // issue next loads; fly during MMA
            #pragma unroll
            for (int r = 0; r < 4; r++) {
                int u = r*256 + t;
                int rr = u >> 5, m4 = (u & 31) * 4;
                kr[r] = *(const uint4*)&kb[(size_t)rr*NPTS + m0 + 128 + m4];
            }
        }
        __syncthreads();
        float acc[4][2][4];
        #pragma unroll
        for (int i = 0; i < 4; i++)
            #pragma unroll
            for (int j = 0; j < 2; j++)
                #pragma unroll
                for (int c = 0; c < 4; c++) acc[i][j][c] = 0.f;
        #pragma unroll
        for (int kh = 0; kh < 32; kh += 8) {
            uint32_t a[4][4], b[2][2];
            #pragma unroll
            for (int ti = 0; ti < 4; ti++) {
                int nb = ti*16 + gq;
                a[ti][0] = Qh[kh+tg][nb];
                a[ti][1] = Qh[kh+tg][nb+8];
                a[ti][2] = Qh[kh+4+tg][nb];
                a[ti][3] = Qh[kh+4+tg][nb+8];
            }
            #pragma unroll
            for (int tj = 0; tj < 2; tj++) {
                int mb = warp*16 + tj*8 + gq;
                b[tj][0] = Kh[kh+tg][mb];
                b[tj][1] = Kh[kh+4+tg][mb];
            }
            #pragma unroll
            for (int ti = 0; ti < 4; ti++)
                #pragma unroll
                for (int tj = 0; tj < 2; tj++)
                    MMA_F16(acc[ti][tj], a[ti], b[tj]);
        }
        // quantize + store + stats on quantized values
        uint32_t us[4][2][2];
        #pragma unroll
        for (int ti = 0; ti < 4; ti++) {
            #pragma unroll
            for (int tj = 0; tj < 2; tj++) {
                int n = n0 + ti*16 + gq;
                int m = m0 + warp*16 + tj*8 + 2*tg;
                uint32_t ulo = h2(acc[ti][tj][0], acc[ti][tj][1]);
                uint32_t uhi = h2(acc[ti][tj][2], acc[ti][tj][3]);
                Su[n*(NPTS/2) + (m >> 1)]     = ulo;
                Su[(n+8)*(NPTS/2) + (m >> 1)] = uhi;
                us[ti][tj][0] = ulo; us[ti][tj][1] = uhi;
            }
            #pragma unroll
            for (int hf = 0; hf < 2; hf++) {
                float2 a0 = h2f(us[ti][0][hf]), a1 = h2f(us[ti][1][hf]);
                float tmax = fmaxf(fmaxf(a0.x, a0.y), fmaxf(a1.x, a1.y));
                float nM = fmaxf(stM[ti][hf], tmax);
                float s = stS[ti][hf] * fexp(stM[ti][hf] - nM);
                s += fexp(a0.x-nM) + fexp(a0.y-nM) + fexp(a1.x-nM) + fexp(a1.y-nM);
                stM[ti][hf] = nM; stS[ti][hf] = s;
            }
        }
    }
    // butterfly over tg lanes, then across 8 warps
    #pragma unroll
    for (int ti = 0; ti < 4; ti++) {
        #pragma unroll
        for (int hf = 0; hf < 2; hf++) {
            float M = stM[ti][hf], Sm = stS[ti][hf];
            #pragma unroll
            for (int off = 1; off <= 2; off <<= 1) {
                float Mo = __shfl_xor_sync(0xffffffffu, M, off);
                float So = __shfl_xor_sync(0xffffffffu, Sm, off);
                float nM = fmaxf(M, Mo);
                Sm = Sm*fexp(M-nM) + So*fexp(Mo-nM);
                M = nM;
            }
            if (tg == 0) {
                int row = ti*16 + gq + 8*hf;
                Mred[row][warp] = M; Sred[row][warp] = Sm;
            }
        }
    }
    __syncthreads();
    if (t < 64) {
        float M = Mred[t][0], Sm = Sred[t][0];
        #pragma unroll
        for (int w = 1; w < 8; w++) {
            float Mo = Mred[t][w], So = Sred[t][w];
            float nM = fmaxf(M, Mo);
            Sm = Sm*fexp(M-nM) + So*fexp(Mo-nM);
            M = nM;
        }
        int idx = bh*NPTS + n0 + t;
        mxv[idx] = M;
        rsv[idx] = 1.f / Sm;
    }
}

// ------- mega dcomp (fp16 MMA, prefetched): xr = v@P + colsum + d + t-GEMM + h ---
__global__ __launch_bounds__(256)
void k_dcomp_mega(const uint32_t* __restrict__ v, const __half* __restrict__ S,
                  const float* __restrict__ mxv, const float* __restrict__ rsv,
                  const float* __restrict__ Wbase, float* __restrict__ h,
                  const float* __restrict__ tb, const float* __restrict__ bng,
                  const float* __restrict__ bnb, int l) {
    __shared__ uint32_t pool[9792];   // 39168 B
    #define VSM(c,n2)  pool[(c)*36 + (n2)]             // main: 0..2304
    #define PSM(n2,m)  pool[2304 + (n2)*72 + (m)]      // main: 2304..4608
    #define MXF(j,n)   (((float*)pool)[4608 + (j)*2048 + (n)])   // main: 4608..8704
    #define WSM(o,c)   (((float*)pool)[(o)*68 + (c)])            // epi: 0..4352
    #define DSM(c,m)   (((float*)pool)[4352 + (c)*68 + (m)])     // epi: 4352..8704
    #define RED(g,m)   (((float*)pool)[8704 + (g)*64 + (m)])     // epi: 8704..9728
    #define CSI(m)     (((float*)pool)[9728 + (m)])              // epi: 9728..9792
    int m0 = blockIdx.x * 64, bh = blockIdx.y, hh = bh & (NH-1);
    int t = threadIdx.x, warp = t >> 5, lane = t & 31;
    int wc = warp >> 2, wm = warp & 3;   // 2x4: each warp 32c x 16m
    int gq = lane >> 2, tg = lane & 3;
    const uint32_t* vb = v + (size_t)bh * 64 * (NPTS/2);
    const uint32_t* Su = (const uint32_t*)(S + (size_t)bh * NPTS * NPTS);
    float* hb = h + (size_t)bh * HDIM * NPTS;
    // preload mx/rs into smem (visible after first loop sync)
    #pragma unroll
    for (int r = 0; r < 2; r++) {
        int u = r*1024 + t*4;
        *(float4*)&MXF(0, u) = *(const float4*)&mxv[bh*NPTS + u];
        *(float4*)&MXF(1, u) = *(const float4*)&rsv[bh*NPTS + u];
    }
    float acc[2][2][4];
    #pragma unroll
    for (int i = 0; i < 2; i++)
        #pragma unroll
        for (int j = 0; j < 2; j++)
            #pragma unroll
            for (int c = 0; c < 4; c++) acc[i][j][c] = 0.f;
    float bsum[4] = {0.f, 0.f, 0.f, 0.f};
    int pr = t >> 4, pm4 = (t & 15) * 4;
    // prefetch chunk 0 (V: 2x uint4; S: 4 rows x uint2)
    uint4 vr[2];
    uint2 sr[4];
    #pragma unroll
    for (int r = 0; r < 2; r++) {
        int u = r*256 + t;
        int c = u >> 3, n2q = (u & 7) * 4;
        vr[r] = *(const uint4*)&vb[(size_t)c*(NPTS/2) + n2q];
    }
    #pragma unroll
    for (int rr = 0; rr < 4; rr++)
        sr[rr] = *(const uint2*)&Su[(size_t)(4*pr+rr)*(NPTS/2) + (m0 >> 1) + (pm4 >> 1)];

    for (int nc = 0; nc < NPTS; nc += 64) {
        __syncthreads();    // prev MMA done; first iter: MXF/prefetch visible
        // STS V
        #pragma unroll
        for (int r = 0; r < 2; r++) {
            int u = r*256 + t;
            int c = u >> 3, n2q = (u & 7) * 4;
            *(uint4*)&VSM(c, n2q) = vr[r];
        }
        // P build from staged S regs + smem stats
        {
            float p[4][4];
            #pragma unroll
            for (int rr = 0; rr < 4; rr++) {
                int n = nc + 4*pr + rr;
                float mx = MXF(0, n), rs = MXF(1, n);
                float2 lo = h2f(sr[rr].x), hi = h2f(sr[rr].y);
                p[rr][0] = fexp(lo.x - mx) * rs;
                p[rr][1] = fexp(lo.y - mx) * rs;
                p[rr][2] = fexp(hi.x - mx) * rs;
                p[rr][3] = fexp(hi.y - mx) * rs;
            }
            #pragma unroll
            for (int j = 0; j < 4; j++)
                bsum[j] += p[0][j] + p[1][j] + p[2][j] + p[3][j];
            uint4 w0 = {h2(p[0][0],p[1][0]), h2(p[0][1],p[1][1]),
                        h2(p[0][2],p[1][2]), h2(p[0][3],p[1][3])};
            uint4 w1 = {h2(p[2][0],p[3][0]), h2(p[2][1],p[3][1]),
                        h2(p[2][2],p[3][2]), h2(p[2][3],p[3][3])};
            *(uint4*)&PSM(2*pr,   pm4) = w0;
            *(uint4*)&PSM(2*pr+1, pm4) = w1;
        }
        // issue next chunk's loads; fly during MMA
        if (nc + 64 < NPTS) {
            #pragma unroll
            for (int r = 0; r < 2; r++) {
                int u = r*256 + t;
                int c = u >> 3, n2q = (u & 7) * 4;
                vr[r] = *(const uint4*)&vb[(size_t)c*(NPTS/2) + ((nc+64) >> 1) + n2q];
            }
            #pragma unroll
            for (int rr = 0; rr < 4; rr++)
                sr[rr] = *(const uint2*)&Su[(size_t)(nc+64 + 4*pr+rr)*(NPTS/2)
                                            + (m0 >> 1) + (pm4 >> 1)];
        }
        __syncthreads();
        // MMA: xr += V(64c x 64n) @ P(64n x 64m), 4 k16 steps
        #pragma unroll
        for (int nh = 0; nh < 32; nh += 8) {
            uint32_t a[2][4], b[2][2];
            #pragma unroll
            for (int ti = 0; ti < 2; ti++) {
                int cb = wc*32 + ti*16 + gq;
                a[ti][0] = VSM(cb,   nh+tg);
                a[ti][1] = VSM(cb+8, nh+tg);
                a[ti][2] = VSM(cb,   nh+4+tg);
                a[ti][3] = VSM(cb+8, nh+4+tg);
            }
            #pragma unroll
            for (int tj = 0; tj < 2; tj++) {
                int mb = wm*16 + tj*8 + gq;
                b[tj][0] = PSM(nh+tg,   mb);
                b[tj][1] = PSM(nh+4+tg, mb);
            }
            #pragma unroll
            for (int ti = 0; ti < 2; ti++)
                #pragma unroll
                for (int tj = 0; tj < 2; tj++)
                    MMA_F16(acc[ti][tj], a[ti], b[tj]);
        }
    }
    __syncthreads();   // main-loop smem free -> epilogue reuse
    #pragma unroll
    for (int j = 0; j < 4; j++) RED(pr, pm4 + j) = bsum[j];
    {
        const float* W = Wbase + (size_t)(l*NH + hh)*HDIM*HDIM;
        #pragma unroll
        for (int r = 0; r < 4; r++) {
            int u = r*1024 + t*4;
            int o = u >> 6, c4 = u & 63;
            *(float4*)&WSM(o, c4) = *(const float4*)&W[o*HDIM + c4];
        }
    }
    __syncthreads();
    if (t < 64) {
        float s = 0.f;
        #pragma unroll
        for (int g = 0; g < 16; g++) s += RED(g, t);
        CSI(t) = 1.f / (1e-9f + s);
    }
    __syncthreads();
    // d = h - xr * csinv  -> DSM
    #pragma unroll
    for (int ti = 0; ti < 2; ti++) {
        #pragma unroll
        for (int tj = 0; tj < 2; tj++) {
            int c = wc*32 + ti*16 + gq;
            int ml = wm*16 + tj*8 + 2*tg;
            float ci0 = CSI(ml), ci1 = CSI(ml+1);
            float2 h0 = *(const float2*)&hb[(size_t)c*NPTS + m0 + ml];
            float2 h1 = *(const float2*)&hb[(size_t)(c+8)*NPTS + m0 + ml];
            DSM(c,   ml)   = h0.x - acc[ti][tj][0]*ci0;
            DSM(c,   ml+1) = h0.y - acc[ti][tj][1]*ci1;
            DSM(c+8, ml)   = h1.x - acc[ti][tj][2]*ci0;
            DSM(c+8, ml+1) = h1.y - acc[ti][tj][3]*ci1;
        }
    }
    __syncthreads();
    // t-GEMM 64x64x64 + BN + relu + residual into h
    {
        int tx = t & 15, ty = t >> 4;
        float a2[4][4] = {};
        #pragma unroll
        for (int cc = 0; cc < 64; cc++) {
            float a[4];
            #pragma unroll
            for (int i = 0; i < 4; i++) a[i] = WSM(ty*4+i, cc);
            float4 bv = *(float4*)&DSM(cc, tx*4);
            float bb[4] = {bv.x, bv.y, bv.z, bv.w};
            #pragma unroll
            for (int i = 0; i < 4; i++)
                #pragma unroll
                for (int j = 0; j < 4; j++)
                    a2[i][j] = fmaf(a[i], bb[j], a2[i][j]);
        }
        int vbase = (l*NH + hh) * HDIM;
        #pragma unroll
        for (int i = 0; i < 4; i++) {
            int o = ty*4 + i;
            float alpha = bng[vbase+o] * rsqrtf(1.f + EPSBN);
            float beta  = tb[vbase+o]*alpha + bnb[vbase+o];
            float* p = &hb[(size_t)o*NPTS + m0 + tx*4];
            float4 hv = *(float4*)p;
            hv.x += fmaxf(fmaf(a2[i][0], alpha, beta), 0.f);
            hv.y += fmaxf(fmaf(a2[i][1], alpha, beta), 0.f);
            hv.z += fmaxf(fmaf(a2[i][2], alpha, beta), 0.f);
            hv.w += fmaxf(fmaf(a2[i][3], alpha, beta), 0.f);
            *(float4*)p = hv;
        }
    }
    #undef VSM
    #undef PSM
    #undef MXF
    #undef WSM
    #undef DSM
    #undef RED
    #undef CSI
}

// ---------------- host orchestration -------------------------------------------------
extern "C" void kernel_launch(void* const* d_in, const int* in_sizes, int n_in,
                              void* d_out, int out_size) {
    const float* x      = (const float*)d_in[0];
    const float* in_w1  = (const float*)d_in[1];
    const float* in_b1  = (const float*)d_in[2];
    const float* in_g1  = (const float*)d_in[3];
    const float* in_be1 = (const float*)d_in[4];
    const float* in_w2  = (const float*)d_in[5];
    const float* in_b2  = (const float*)d_in[6];
    const float* in_g2  = (const float*)d_in[7];
    const float* in_be2 = (const float*)d_in[8];
    const float* q_w    = (const float*)d_in[9];
    const float* k_w    = (const float*)d_in[10];
    const float* v_w    = (const float*)d_in[11];
    const float* v_b    = (const float*)d_in[12];
    const float* t_w    = (const float*)d_in[13];
    const float* t_b    = (const float*)d_in[14];
    const float* bn_g   = (const float*)d_in[15];
    const float* bn_b   = (const float*)d_in[16];
    const float* proj_w = (const float*)d_in[17];
    const float* proj_b = (const float*)d_in[18];

    float *hA, *hB, *mxv, *rsv;
    uint32_t *qh, *kh, *vh;
    __half *Sh;
    cudaGetSymbolAddress((void**)&hA,  g_bufA);
    cudaGetSymbolAddress((void**)&hB,  g_bufB);
    cudaGetSymbolAddress((void**)&qh,  g_qh);
    cudaGetSymbolAddress((void**)&kh,  g_kh);
    cudaGetSymbolAddress((void**)&vh,  g_vh);
    cudaGetSymbolAddress((void**)&Sh,  g_Sh);
    cudaGetSymbolAddress((void**)&mxv, g_mx);
    cudaGetSymbolAddress((void**)&rsv, g_rs);

    dim3 ttb(32, 8);
    k_transpose_in<<<dim3(NPTS/32, CCH/32, BNB), ttb>>>(x, hA);

    k_mlp<<<dim3(NPTS/128, CCH/64, BNB), 256>>>(in_w1, hA, hB, in_b1, in_g1, in_be1, 1);
    k_mlp<<<dim3(NPTS/128, CCH/64, BNB), 256>>>(in_w2, hB, hA, in_b2, in_g2, in_be2, 1);

    float* h = hA;
    float* o = hB;
    for (int l = 0; l < NL; l++) {
        k_qkv<<<dim3(NPTS/128, BHN), 256>>>(q_w, k_w, v_w, v_b, h, qh, kh, vh, l);
        k_scores_st<<<dim3(NPTS/64, BHN), 256>>>(qh, kh, Sh, mxv, rsv);
        k_dcomp_mega<<<dim3(NPTS/64, BHN), 256>>>(vh, Sh, mxv, rsv, t_w, h,
                                                  t_b, bn_g, bn_b, l);
        k_mlp<<<dim3(NPTS/128, CCH/64, BNB), 256>>>(proj_w + (size_t)l*CCH*CCH, h, o,
                                                    proj_b + (size_t)l*CCH,
                                                    nullptr, nullptr, 0);
        float* tmp = h; h = o; o = tmp;
    }

    k_transpose_out<<<dim3(CCH/32, NPTS/32, BNB), ttb>>>(h, (float*)d_out);
}

// round 12
// speedup vs baseline: 2.0950x; 1.1824x over previous
#include <cuda_runtime.h>
#include <cuda_fp16.h>
#include <math.h>
#include <stdint.h>

#define BNB  2
#define NPTS 2048
#define CCH  256
#define NH   4
#define HDIM 64
#define NL   4
#define BHN  (BNB*NH)
#define EPSBN 1e-5f

// ---------------- scratch (device globals; no allocation allowed) -------------
__device__ float    g_bufA[BNB*CCH*NPTS];
__device__ float    g_bufB[BNB*CCH*NPTS];
__device__ uint32_t g_qh[BHN*32*NPTS];        // q packed half2 along o: [bh][o2][n]
__device__ uint32_t g_kh[BHN*32*NPTS];        // k packed half2 along o: [bh][o2][m]
__device__ uint32_t g_vh[BHN*64*(NPTS/2)];    // v packed half2 along n: [bh][c][n2]
__device__ __half   g_Sh[(size_t)BHN*NPTS*NPTS];  // raw scores fp16 (67MB, L2-resident)
__device__ float    g_rs[BHN*NPTS];           // 1 / rowsum(exp(S))  (no max shift)

// fast exp on the FMA pipe
__device__ __forceinline__ float fexp(float x) {
    x = fmaxf(x, -80.f);
    float t = fmaf(x, 1.44269504f, 12582912.f);
    int   e = __float_as_int(t) << 23;
    float r = t - 12582912.f;
    float f = fmaf(x, 1.44269504f, -r);
    float p = 1.54035304e-4f;
    p = fmaf(p, f, 1.33335581e-3f);
    p = fmaf(p, f, 9.61812911e-3f);
    p = fmaf(p, f, 5.55041087e-2f);
    p = fmaf(p, f, 2.40226507e-1f);
    p = fmaf(p, f, 6.93147181e-1f);
    p = fmaf(p, f, 1.0f);
    return __int_as_float(__float_as_int(p) + e);
}

__device__ __forceinline__ uint32_t h2(float a, float b) {
    __half2 h = __floats2half2_rn(a, b);
    return *reinterpret_cast<uint32_t*>(&h);
}
__device__ __forceinline__ float2 h2f(uint32_t u) {
    return __half22float2(*reinterpret_cast<__half2*>(&u));
}

#define MMA_F16(c, a, b)                                                         \
    asm volatile("mma.sync.aligned.m16n8k16.row.col.f32.f16.f16.f32 "            \
                 "{%0,%1,%2,%3},{%4,%5,%6,%7},{%8,%9},{%0,%1,%2,%3};"            \
                 : "+f"((c)[0]), "+f"((c)[1]), "+f"((c)[2]), "+f"((c)[3])        \
                 : "r"((a)[0]), "r"((a)[1]), "r"((a)[2]), "r"((a)[3]),           \
                   "r"((b)[0]), "r"((b)[1]))

// ---------------- transposes ----------------
__global__ void k_transpose_in(const float* __restrict__ x, float* __restrict__ h) {
    __shared__ float tile[32][33];
    int b = blockIdx.z;
    int n0 = blockIdx.x * 32, c0 = blockIdx.y * 32;
    int tx = threadIdx.x, ty = threadIdx.y;
    for (int i = ty; i < 32; i += 8)
        tile[i][tx] = x[(size_t)b*NPTS*CCH + (size_t)(n0+i)*CCH + c0 + tx];
    __syncthreads();
    for (int i = ty; i < 32; i += 8)
        h[(size_t)b*CCH*NPTS + (size_t)(c0+i)*NPTS + n0 + tx] = tile[tx][i];
}

__global__ void k_transpose_out(const float* __restrict__ h, float* __restrict__ out) {
    __shared__ float tile[32][33];
    int b = blockIdx.z;
    int c0 = blockIdx.x * 32, n0 = blockIdx.y * 32;
    int tx = threadIdx.x, ty = threadIdx.y;
    for (int i = ty; i < 32; i += 8)
        tile[i][tx] = h[(size_t)b*CCH*NPTS + (size_t)(c0+i)*NPTS + n0 + tx];
    __syncthreads();
    for (int i = ty; i < 32; i += 8)
        out[(size_t)b*NPTS*CCH + (size_t)(n0+i)*CCH + c0 + tx] = tile[tx][i];
}

// ---------------- full-channel GEMM (MLP / proj), pipelined ----------------
__global__ __launch_bounds__(256)
void k_mlp(const float* __restrict__ W, const float* __restrict__ in,
           float* __restrict__ out, const float* __restrict__ bvec,
           const float* __restrict__ gvec, const float* __restrict__ bevec,
           int relu) {
    __shared__ float As[64][16];
    __shared__ float Bs[16][128];
    int b  = blockIdx.z;
    int n0 = blockIdx.x * 128, o0 = blockIdx.y * 64;
    int t  = threadIdx.x, tx = t & 15, ty = t >> 4;
    const float* inb = in + (size_t)b*CCH*NPTS;
    int aoo = t >> 2, akk = (t & 3) * 4;
    int bk0 = (t*4) >> 7,        bn0 = (t*4) & 127;
    int bk1 = (1024 + t*4) >> 7, bn1 = (1024 + t*4) & 127;
    float acc[4][8] = {};
    // prefetch kc = 0
    float4 war  = *(const float4*)&W[(size_t)(o0+aoo)*CCH + akk];
    float4 wbr0 = *(const float4*)&inb[(size_t)bk0*NPTS + n0 + bn0];
    float4 wbr1 = *(const float4*)&inb[(size_t)bk1*NPTS + n0 + bn1];
    for (int kc = 0; kc < CCH; kc += 16) {
        if (kc) __syncthreads();
        *(float4*)&As[aoo][akk] = war;
        *(float4*)&Bs[bk0][bn0] = wbr0;
        *(float4*)&Bs[bk1][bn1] = wbr1;
        if (kc + 16 < CCH) {     // issue next loads; fly during compute
            war  = *(const float4*)&W[(size_t)(o0+aoo)*CCH + kc + 16 + akk];
            wbr0 = *(const float4*)&inb[(size_t)(kc+16+bk0)*NPTS + n0 + bn0];
            wbr1 = *(const float4*)&inb[(size_t)(kc+16+bk1)*NPTS + n0 + bn1];
        }
        __syncthreads();
        #pragma unroll
        for (int kk = 0; kk < 16; kk++) {
            float a[4];
            #pragma unroll
            for (int i = 0; i < 4; i++) a[i] = As[ty*4+i][kk];
            float4 b0 = *(float4*)&Bs[kk][tx*8];
            float4 b1 = *(float4*)&Bs[kk][tx*8+4];
            float bb[8] = {b0.x,b0.y,b0.z,b0.w,b1.x,b1.y,b1.z,b1.w};
            #pragma unroll
            for (int i = 0; i < 4; i++)
                #pragma unroll
                for (int j = 0; j < 8; j++)
                    acc[i][j] = fmaf(a[i], bb[j], acc[i][j]);
        }
    }
    float* outb = out + (size_t)b*CCH*NPTS;
    #pragma unroll
    for (int i = 0; i < 4; i++) {
        int o = o0 + ty*4 + i;
        float alpha = 1.f, beta = 0.f;
        if (gvec) { alpha = gvec[o] * rsqrtf(1.f + EPSBN); beta = bvec[o]*alpha + bevec[o]; }
        else if (bvec) beta = bvec[o];
        float vv[8];
        #pragma unroll
        for (int j = 0; j < 8; j++) {
            vv[j] = fmaf(acc[i][j], alpha, beta);
            if (relu) vv[j] = fmaxf(vv[j], 0.f);
        }
        float4 s0 = {vv[0],vv[1],vv[2],vv[3]}, s1 = {vv[4],vv[5],vv[6],vv[7]};
        float* p = &outb[(size_t)o*NPTS + n0 + tx*8];
        *(float4*)p = s0; *(float4*)(p+4) = s1;
    }
}

// ------- fused q/k/v head GEMMs: fp32 compute, half2-packed outputs -----------
// q,k: [o2=32][n] packed along o. v: [c=64][n2] packed along n. W prefetched.
__global__ __launch_bounds__(256)
void k_qkv(const float* __restrict__ qw, const float* __restrict__ kw,
           const float* __restrict__ vw, const float* __restrict__ vbias,
           const float* __restrict__ in, uint32_t* __restrict__ qo,
           uint32_t* __restrict__ ko, uint32_t* __restrict__ vo, int l) {
    __shared__ float As[64][64];
    __shared__ float Bs[64][128];
    int n0 = blockIdx.x * 128, bh = blockIdx.y, hh = bh & (NH-1);
    int t = threadIdx.x, tx = t & 15, ty = t >> 4;
    const float* inb = in + (size_t)bh * HDIM * NPTS;
    int vbase = (l*NH + hh) * HDIM;
    size_t wof = (size_t)(l*NH + hh)*HDIM*HDIM;
    const float* Wp[3] = {qw + wof, kw + wof, vw + wof};
    // prefetch W0 while issuing B loads
    float4 wr[4];
    #pragma unroll
    for (int r = 0; r < 4; r++) wr[r] = ((const float4*)Wp[0])[t + r*256];
    #pragma unroll
    for (int r = 0; r < 8; r++) {
        int idx = r*1024 + t*4;
        int cc = idx >> 7, nn = idx & 127;
        *(float4*)&Bs[cc][nn] = *(const float4*)&inb[(size_t)cc*NPTS + n0 + nn];
    }
    for (int w = 0; w < 3; w++) {
        if (w) __syncthreads();
        #pragma unroll
        for (int r = 0; r < 4; r++)
            ((float4*)As)[t + r*256] = wr[r];
        if (w < 2) {
            #pragma unroll
            for (int r = 0; r < 4; r++) wr[r] = ((const float4*)Wp[w+1])[t + r*256];
        }
        __syncthreads();
        float acc[4][8] = {};
        #pragma unroll
        for (int cc = 0; cc < 64; cc++) {
            float a[4];
            #pragma unroll
            for (int i = 0; i < 4; i++) a[i] = As[ty*4+i][cc];
            float4 b0 = *(float4*)&Bs[cc][tx*8];
            float4 b1 = *(float4*)&Bs[cc][tx*8+4];
            float bb[8] = {b0.x,b0.y,b0.z,b0.w,b1.x,b1.y,b1.z,b1.w};
            #pragma unroll
            for (int i = 0; i < 4; i++)
                #pragma unroll
                for (int j = 0; j < 8; j++)
                    acc[i][j] = fmaf(a[i], bb[j], acc[i][j]);
        }
        if (w < 2) {
            uint32_t* outb = (w == 0 ? qo : ko) + (size_t)bh * 32 * NPTS;
            #pragma unroll
            for (int pp = 0; pp < 2; pp++) {
                int i0 = pp*2;
                uint4 u0 = {h2(acc[i0][0],acc[i0+1][0]), h2(acc[i0][1],acc[i0+1][1]),
                            h2(acc[i0][2],acc[i0+1][2]), h2(acc[i0][3],acc[i0+1][3])};
                uint4 u1 = {h2(acc[i0][4],acc[i0+1][4]), h2(acc[i0][5],acc[i0+1][5]),
                            h2(acc[i0][6],acc[i0+1][6]), h2(acc[i0][7],acc[i0+1][7])};
                uint32_t* p = &outb[(size_t)(ty*2+pp)*NPTS + n0 + tx*8];
                *(uint4*)p = u0; *(uint4*)(p+4) = u1;
            }
        } else {
            uint32_t* outb = vo + (size_t)bh * 64 * (NPTS/2);
            #pragma unroll
            for (int i = 0; i < 4; i++) {
                float bb = vbias[vbase + ty*4 + i];
                uint4 u = {h2(acc[i][0]+bb, acc[i][1]+bb), h2(acc[i][2]+bb, acc[i][3]+bb),
                           h2(acc[i][4]+bb, acc[i][5]+bb), h2(acc[i][6]+bb, acc[i][7]+bb)};
                *(uint4*)&outb[(size_t)(ty*4+i)*(NPTS/2) + ((n0 + tx*8) >> 1)] = u;
            }
        }
    }
}

// ---- scores + online rowsum (NO max shift), fp16 MMA, prefetched K chunks ----
// block = 64 n-rows x full m sweep (chunks of 128). S stored as half.
// rowsum computed on the QUANTIZED (stored) values for consistency with dcomp.
__global__ __launch_bounds__(256)
void k_scores_st(const uint32_t* __restrict__ q, const uint32_t* __restrict__ k,
                 __half* __restrict__ S, float* __restrict__ rsv) {
    __shared__ uint32_t Qh[32][72];    // [o2][n]
    __shared__ uint32_t Kh[32][136];   // [o2][m]
    __shared__ float Sred[64][8];
    int n0 = blockIdx.x * 64, bh = blockIdx.y;
    const uint32_t* qb = q + (size_t)bh * 32 * NPTS;
    const uint32_t* kb = k + (size_t)bh * 32 * NPTS;
    uint32_t* Su = (uint32_t*)(S + (size_t)bh * NPTS * NPTS);
    int t = threadIdx.x, warp = t >> 5, lane = t & 31;
    int gq = lane >> 2, tg = lane & 3;
    // persistent Q tile 32o2 x 64n
    #pragma unroll
    for (int r = 0; r < 2; r++) {
        int u = r*256 + t;
        int rr = u >> 4, n4 = (u & 15) * 4;
        *(uint4*)&Qh[rr][n4] = *(const uint4*)&qb[(size_t)rr*NPTS + n0 + n4];
    }
    float stS[4][2];
    #pragma unroll
    for (int i = 0; i < 4; i++)
        #pragma unroll
        for (int hf = 0; hf < 2; hf++) stS[i][hf] = 0.f;
    // prefetch K chunk 0
    uint4 kr[4];
    #pragma unroll
    for (int r = 0; r < 4; r++) {
        int u = r*256 + t;
        int rr = u >> 5, m4 = (u & 31) * 4;
        kr[r] = *(const uint4*)&kb[(size_t)rr*NPTS + m4];
    }
    for (int m0 = 0; m0 < NPTS; m0 += 128) {
        __syncthreads();                  // prev MMA done reading Kh
        #pragma unroll
        for (int r = 0; r < 4; r++) {
            int u = r*256 + t;
            int rr = u >> 5, m4 = (u & 31) * 4;
            *(uint4*)&Kh[rr][m4] = kr[r];
        }
        if (m0 + 128 < NPTS) {            // issue next loads; fly during MMA
            #pragma unroll
            for (int r = 0; r < 4; r++) {
                int u = r*256 + t;
                int rr = u >> 5, m4 = (u & 31) * 4;
                kr[r] = *(const uint4*)&kb[(size_t)rr*NPTS + m0 + 128 + m4];
            }
        }
        __syncthreads();
        float acc[4][2][4];
        #pragma unroll
        for (int i = 0; i < 4; i++)
            #pragma unroll
            for (int j = 0; j < 2; j++)
                #pragma unroll
                for (int c = 0; c < 4; c++) acc[i][j][c] = 0.f;
        #pragma unroll
        for (int kh = 0; kh < 32; kh += 8) {
            uint32_t a[4][4], b[2][2];
            #pragma unroll
            for (int ti = 0; ti < 4; ti++) {
                int nb = ti*16 + gq;
                a[ti][0] = Qh[kh+tg][nb];
                a[ti][1] = Qh[kh+tg][nb+8];
                a[ti][2] = Qh[kh+4+tg][nb];
                a[ti][3] = Qh[kh+4+tg][nb+8];
            }
            #pragma unroll
            for (int tj = 0; tj < 2; tj++) {
                int mb = warp*16 + tj*8 + gq;
                b[tj][0] = Kh[kh+tg][mb];
                b[tj][1] = Kh[kh+4+tg][mb];
            }
            #pragma unroll
            for (int ti = 0; ti < 4; ti++)
                #pragma unroll
                for (int tj = 0; tj < 2; tj++)
                    MMA_F16(acc[ti][tj], a[ti], b[tj]);
        }
        // quantize + store + rowsum on quantized values (no max shift)
        #pragma unroll
        for (int ti = 0; ti < 4; ti++) {
            uint32_t us[2][2];
            #pragma unroll
            for (int tj = 0; tj < 2; tj++) {
                int n = n0 + ti*16 + gq;
                int m = m0 + warp*16 + tj*8 + 2*tg;
                uint32_t ulo = h2(acc[ti][tj][0], acc[ti][tj][1]);
                uint32_t uhi = h2(acc[ti][tj][2], acc[ti][tj][3]);
                Su[n*(NPTS/2) + (m >> 1)]     = ulo;
                Su[(n+8)*(NPTS/2) + (m >> 1)] = uhi;
                us[tj][0] = ulo; us[tj][1] = uhi;
            }
            #pragma unroll
            for (int hf = 0; hf < 2; hf++) {
                float2 a0 = h2f(us[0][hf]), a1 = h2f(us[1][hf]);
                stS[ti][hf] += fexp(a0.x) + fexp(a0.y) + fexp(a1.x) + fexp(a1.y);
            }
        }
    }
    // plain-sum butterfly over tg lanes, then across 8 warps
    #pragma unroll
    for (int ti = 0; ti < 4; ti++) {
        #pragma unroll
        for (int hf = 0; hf < 2; hf++) {
            float Sm = stS[ti][hf];
            Sm += __shfl_xor_sync(0xffffffffu, Sm, 1);
            Sm += __shfl_xor_sync(0xffffffffu, Sm, 2);
            if (tg == 0) {
                int row = ti*16 + gq + 8*hf;
                Sred[row][warp] = Sm;
            }
        }
    }
    __syncthreads();
    if (t < 64) {
        float Sm = 0.f;
        #pragma unroll
        for (int w = 0; w < 8; w++) Sm += Sred[t][w];
        rsv[bh*NPTS + n0 + t] = 1.f / Sm;
    }
}

// ------- mega dcomp (fp16 MMA, prefetched): xr = v@P + colsum + d + t-GEMM + h ---
__global__ __launch_bounds__(256)
void k_dcomp_mega(const uint32_t* __restrict__ v, const __half* __restrict__ S,
                  const float* __restrict__ rsv, const float* __restrict__ Wbase,
                  float* __restrict__ h, const float* __restrict__ tb,
                  const float* __restrict__ bng, const float* __restrict__ bnb,
                  int l) {
    __shared__ uint32_t pool[9792];   // 39168 B
    #define VSM(c,n2)  pool[(c)*36 + (n2)]             // main: 0..2304
    #define PSM(n2,m)  pool[2304 + (n2)*72 + (m)]      // main: 2304..4608
    #define RSF(n)     (((float*)pool)[4608 + (n)])            // main: 4608..6656
    #define WSM(o,c)   (((float*)pool)[(o)*68 + (c)])          // epi: 0..4352
    #define DSM(c,m)   (((float*)pool)[4352 + (c)*68 + (m)])   // epi: 4352..8704
    #define RED(g,m)   (((float*)pool)[8704 + (g)*64 + (m)])   // epi: 8704..9728
    #define CSI(m)     (((float*)pool)[9728 + (m)])            // epi: 9728..9792
    int m0 = blockIdx.x * 64, bh = blockIdx.y, hh = bh & (NH-1);
    int t = threadIdx.x, warp = t >> 5, lane = t & 31;
    int wc = warp >> 2, wm = warp & 3;   // 2x4: each warp 32c x 16m
    int gq = lane >> 2, tg = lane & 3;
    const uint32_t* vb = v + (size_t)bh * 64 * (NPTS/2);
    const uint32_t* Su = (const uint32_t*)(S + (size_t)bh * NPTS * NPTS);
    float* hb = h + (size_t)bh * HDIM * NPTS;
    // preload rs into smem (visible after first loop sync)
    #pragma unroll
    for (int r = 0; r < 2; r++) {
        int u = r*1024 + t*4;
        *(float4*)&RSF(u) = *(const float4*)&rsv[bh*NPTS + u];
    }
    float acc[2][2][4];
    #pragma unroll
    for (int i = 0; i < 2; i++)
        #pragma unroll
        for (int j = 0; j < 2; j++)
            #pragma unroll
            for (int c = 0; c < 4; c++) acc[i][j][c] = 0.f;
    float bsum[4] = {0.f, 0.f, 0.f, 0.f};
    int pr = t >> 4, pm4 = (t & 15) * 4;
    // prefetch chunk 0 (V: 2x uint4; S: 4 rows x uint2)
    uint4 vr[2];
    uint2 sr[4];
    #pragma unroll
    for (int r = 0; r < 2; r++) {
        int u = r*256 + t;
        int c = u >> 3, n2q = (u & 7) * 4;
        vr[r] = *(const uint4*)&vb[(size_t)c*(NPTS/2) + n2q];
    }
    #pragma unroll
    for (int rr = 0; rr < 4; rr++)
        sr[rr] = *(const uint2*)&Su[(size_t)(4*pr+rr)*(NPTS/2) + (m0 >> 1) + (pm4 >> 1)];

    for (int nc = 0; nc < NPTS; nc += 64) {
        __syncthreads();    // prev MMA done; first iter: RSF/prefetch visible
        // STS V
        #pragma unroll
        for (int r = 0; r < 2; r++) {
            int u = r*256 + t;
            int c = u >> 3, n2q = (u & 7) * 4;
            *(uint4*)&VSM(c, n2q) = vr[r];
        }
        // P build from staged S regs + smem rs (no max shift)
        {
            float p[4][4];
            #pragma unroll
            for (int rr = 0; rr < 4; rr++) {
                float rs = RSF(nc + 4*pr + rr);
                float2 lo = h2f(sr[rr].x), hi = h2f(sr[rr].y);
                p[rr][0] = fexp(lo.x) * rs;
                p[rr][1] = fexp(lo.y) * rs;
                p[rr][2] = fexp(hi.x) * rs;
                p[rr][3] = fexp(hi.y) * rs;
            }
            #pragma unroll
            for (int j = 0; j < 4; j++)
                bsum[j] += p[0][j] + p[1][j] + p[2][j] + p[3][j];
            uint4 w0 = {h2(p[0][0],p[1][0]), h2(p[0][1],p[1][1]),
                        h2(p[0][2],p[1][2]), h2(p[0][3],p[1][3])};
            uint4 w1 = {h2(p[2][0],p[3][0]), h2(p[2][1],p[3][1]),
                        h2(p[2][2],p[3][2]), h2(p[2][3],p[3][3])};
            *(uint4*)&PSM(2*pr,   pm4) = w0;
            *(uint4*)&PSM(2*pr+1, pm4) = w1;
        }
        // issue next chunk's loads; fly during MMA
        if (nc + 64 < NPTS) {
            #pragma unroll
            for (int r = 0; r < 2; r++) {
                int u = r*256 + t;
                int c = u >> 3, n2q = (u & 7) * 4;
                vr[r] = *(const uint4*)&vb[(size_t)c*(NPTS/2) + ((nc+64) >> 1) + n2q];
            }
            #pragma unroll
            for (int rr = 0; rr < 4; rr++)
                sr[rr] = *(const uint2*)&Su[(size_t)(nc+64 + 4*pr+rr)*(NPTS/2)
                                            + (m0 >> 1) + (pm4 >> 1)];
        }
        __syncthreads();
        // MMA: xr += V(64c x 64n) @ P(64n x 64m), 4 k16 steps
        #pragma unroll
        for (int nh = 0; nh < 32; nh += 8) {
            uint32_t a[2][4], b[2][2];
            #pragma unroll
            for (int ti = 0; ti < 2; ti++) {
                int cb = wc*32 + ti*16 + gq;
                a[ti][0] = VSM(cb,   nh+tg);
                a[ti][1] = VSM(cb+8, nh+tg);
                a[ti][2] = VSM(cb,   nh+4+tg);
                a[ti][3] = VSM(cb+8, nh+4+tg);
            }
            #pragma unroll
            for (int tj = 0; tj < 2; tj++) {
                int mb = wm*16 + tj*8 + gq;
                b[tj][0] = PSM(nh+tg,   mb);
                b[tj][1] = PSM(nh+4+tg, mb);
            }
            #pragma unroll
            for (int ti = 0; ti < 2; ti++)
                #pragma unroll
                for (int tj = 0; tj < 2; tj++)
                    MMA_F16(acc[ti][tj], a[ti], b[tj]);
        }
    }
    __syncthreads();   // main-loop smem free -> epilogue reuse
    #pragma unroll
    for (int j = 0; j < 4; j++) RED(pr, pm4 + j) = bsum[j];
    {
        const float* W = Wbase + (size_t)(l*NH + hh)*HDIM*HDIM;
        #pragma unroll
        for (int r = 0; r < 4; r++) {
            int u = r*1024 + t*4;
            int o = u >> 6, c4 = u & 63;
            *(float4*)&WSM(o, c4) = *(const float4*)&W[o*HDIM + c4];
        }
    }
    __syncthreads();
    if (t < 64) {
        float s = 0.f;
        #pragma unroll
        for (int g = 0; g < 16; g++) s += RED(g, t);
        CSI(t) = 1.f / (1e-9f + s);
    }
    __syncthreads();
    // d = h - xr * csinv  -> DSM
    #pragma unroll
    for (int ti = 0; ti < 2; ti++) {
        #pragma unroll
        for (int tj = 0; tj < 2; tj++) {
            int c = wc*32 + ti*16 + gq;
            int ml = wm*16 + tj*8 + 2*tg;
            float ci0 = CSI(ml), ci1 = CSI(ml+1);
            float2 h0 = *(const float2*)&hb[(size_t)c*NPTS + m0 + ml];
            float2 h1 = *(const float2*)&hb[(size_t)(c+8)*NPTS + m0 + ml];
            DSM(c,   ml)   = h0.x - acc[ti][tj][0]*ci0;
            DSM(c,   ml+1) = h0.y - acc[ti][tj][1]*ci1;
            DSM(c+8, ml)   = h1.x - acc[ti][tj][2]*ci0;
            DSM(c+8, ml+1) = h1.y - acc[ti][tj][3]*ci1;
        }
    }
    __syncthreads();
    // t-GEMM 64x64x64 + BN + relu + residual into h
    {
        int tx = t & 15, ty = t >> 4;
        float a2[4][4] = {};
        #pragma unroll
        for (int cc = 0; cc < 64; cc++) {
            float a[4];
            #pragma unroll
            for (int i = 0; i < 4; i++) a[i] = WSM(ty*4+i, cc);
            float4 bv = *(float4*)&DSM(cc, tx*4);
            float bb[4] = {bv.x, bv.y, bv.z, bv.w};
            #pragma unroll
            for (int i = 0; i < 4; i++)
                #pragma unroll
                for (int j = 0; j < 4; j++)
                    a2[i][j] = fmaf(a[i], bb[j], a2[i][j]);
        }
        int vbase = (l*NH + hh) * HDIM;
        #pragma unroll
        for (int i = 0; i < 4; i++) {
            int o = ty*4 + i;
            float alpha = bng[vbase+o] * rsqrtf(1.f + EPSBN);
            float beta  = tb[vbase+o]*alpha + bnb[vbase+o];
            float* p = &hb[(size_t)o*NPTS + m0 + tx*4];
            float4 hv = *(float4*)p;
            hv.x += fmaxf(fmaf(a2[i][0], alpha, beta), 0.f);
            hv.y += fmaxf(fmaf(a2[i][1], alpha, beta), 0.f);
            hv.z += fmaxf(fmaf(a2[i][2], alpha, beta), 0.f);
            hv.w += fmaxf(fmaf(a2[i][3], alpha, beta), 0.f);
            *(float4*)p = hv;
        }
    }
    #undef VSM
    #undef PSM
    #undef RSF
    #undef WSM
    #undef DSM
    #undef RED
    #undef CSI
}

// ---------------- host orchestration -------------------------------------------------
extern "C" void kernel_launch(void* const* d_in, const int* in_sizes, int n_in,
                              void* d_out, int out_size) {
    const float* x      = (const float*)d_in[0];
    const float* in_w1  = (const float*)d_in[1];
    const float* in_b1  = (const float*)d_in[2];
    const float* in_g1  = (const float*)d_in[3];
    const float* in_be1 = (const float*)d_in[4];
    const float* in_w2  = (const float*)d_in[5];
    const float* in_b2  = (const float*)d_in[6];
    const float* in_g2  = (const float*)d_in[7];
    const float* in_be2 = (const float*)d_in[8];
    const float* q_w    = (const float*)d_in[9];
    const float* k_w    = (const float*)d_in[10];
    const float* v_w    = (const float*)d_in[11];
    const float* v_b    = (const float*)d_in[12];
    const float* t_w    = (const float*)d_in[13];
    const float* t_b    = (const float*)d_in[14];
    const float* bn_g   = (const float*)d_in[15];
    const float* bn_b   = (const float*)d_in[16];
    const float* proj_w = (const float*)d_in[17];
    const float* proj_b = (const float*)d_in[18];

    float *hA, *hB, *rsv;
    uint32_t *qh, *kh, *vh;
    __half *Sh;
    cudaGetSymbolAddress((void**)&hA,  g_bufA);
    cudaGetSymbolAddress((void**)&hB,  g_bufB);
    cudaGetSymbolAddress((void**)&qh,  g_qh);
    cudaGetSymbolAddress((void**)&kh,  g_kh);
    cudaGetSymbolAddress((void**)&vh,  g_vh);
    cudaGetSymbolAddress((void**)&Sh,  g_Sh);
    cudaGetSymbolAddress((void**)&rsv, g_rs);

    dim3 ttb(32, 8);
    k_transpose_in<<<dim3(NPTS/32, CCH/32, BNB), ttb>>>(x, hA);

    k_mlp<<<dim3(NPTS/128, CCH/64, BNB), 256>>>(in_w1, hA, hB, in_b1, in_g1, in_be1, 1);
    k_mlp<<<dim3(NPTS/128, CCH/64, BNB), 256>>>(in_w2, hB, hA, in_b2, in_g2, in_be2, 1);

    float* h = hA;
    float* o = hB;
    for (int l = 0; l < NL; l++) {
        k_qkv<<<dim3(NPTS/128, BHN), 256>>>(q_w, k_w, v_w, v_b, h, qh, kh, vh, l);
        k_scores_st<<<dim3(NPTS/64, BHN), 256>>>(qh, kh, Sh, rsv);
        k_dcomp_mega<<<dim3(NPTS/64, BHN), 256>>>(vh, Sh, rsv, t_w, h,
                                                  t_b, bn_g, bn_b, l);
        k_mlp<<<dim3(NPTS/128, CCH/64, BNB), 256>>>(proj_w + (size_t)l*CCH*CCH, h, o,
                                                    proj_b + (size_t)l*CCH,
                                                    nullptr, nullptr, 0);
        float* tmp = h; h = o; o = tmp;
    }

    k_transpose_out<<<dim3(CCH/32, NPTS/32, BNB), ttb>>>(h, (float*)d_out);
}